// round 3
// baseline (speedup 1.0000x reference)
#include <cuda_runtime.h>

#define NMAX 100000
#define EMAX 1600000
#define FULLMASK 0xffffffffu
#define SCAN_B 1024

// ---------------- scratch (static device globals; no allocation) ----------------
__device__ float  g_h[NMAX * 64];       // h = x @ W for current layer
__device__ float  g_x[NMAX * 64];       // current layer input (post-elu)
__device__ float  g_init[NMAX * 64];    // initial_x (pre-elu output of first conv)
__device__ float2 g_asrc[NMAX];         // per-node attention dot, src side (2 heads)
__device__ float2 g_adst[NMAX];         // per-node attention dot, dst side (2 heads)
__device__ int    g_cnt[NMAX];
__device__ int    g_rowptr[NMAX + 1];
__device__ int    g_cursor[NMAX];
__device__ int    g_colsrc[EMAX + NMAX];
__device__ float  g_hout[NMAX];
__device__ int    g_bsums[1024];

// ---------------- CSR build (by destination node) ----------------
__global__ void init_cnt(int n) {
    int i = blockIdx.x * blockDim.x + threadIdx.x;
    if (i < n) g_cnt[i] = 1;  // self loop
}

__global__ void hist(const int* __restrict__ ei, int e) {
    int i = blockIdx.x * blockDim.x + threadIdx.x;
    if (i < e) atomicAdd(&g_cnt[ei[e + i]], 1);
}

__global__ void scan1(int n) {
    __shared__ int sh[SCAN_B];
    int i = blockIdx.x * SCAN_B + threadIdx.x;
    int v = (i < n) ? g_cnt[i] : 0;
    sh[threadIdx.x] = v;
    __syncthreads();
    for (int off = 1; off < SCAN_B; off <<= 1) {
        int t = (threadIdx.x >= off) ? sh[threadIdx.x - off] : 0;
        __syncthreads();
        sh[threadIdx.x] += t;
        __syncthreads();
    }
    if (i < n) g_rowptr[i] = sh[threadIdx.x] - v;  // exclusive
    if (threadIdx.x == SCAN_B - 1) g_bsums[blockIdx.x] = sh[threadIdx.x];
}

__global__ void scan2(int nb) {
    __shared__ int sh[SCAN_B];
    int v = (threadIdx.x < nb) ? g_bsums[threadIdx.x] : 0;
    sh[threadIdx.x] = v;
    __syncthreads();
    for (int off = 1; off < SCAN_B; off <<= 1) {
        int t = (threadIdx.x >= off) ? sh[threadIdx.x - off] : 0;
        __syncthreads();
        sh[threadIdx.x] += t;
        __syncthreads();
    }
    if (threadIdx.x < nb) g_bsums[threadIdx.x] = sh[threadIdx.x] - v;  // exclusive
}

__global__ void scan3(int n, int total) {
    int i = blockIdx.x * SCAN_B + threadIdx.x;
    if (i < n) {
        int v = g_rowptr[i] + g_bsums[blockIdx.x];
        g_rowptr[i] = v;
        g_cursor[i] = v;
    }
    if (i == 0) g_rowptr[n] = total;
}

__global__ void scatter(const int* __restrict__ ei, int e, int n) {
    int i = blockIdx.x * blockDim.x + threadIdx.x;
    if (i < e) {
        int src = ei[i];
        int dst = ei[e + i];
        int pos = atomicAdd(&g_cursor[dst], 1);
        g_colsrc[pos] = src;
    } else if (i < e + n) {
        int v = i - e;  // self loop
        int pos = atomicAdd(&g_cursor[v], 1);
        g_colsrc[pos] = v;
    }
}

// ---------------- GEMM: h = X @ W   (X:[n,K], W:[K,64] row-major) ----------------
// 64x64 block tile, 16x16 threads, 4x4 register micro-tile.
template <int K>
__global__ void gemm_tile(const float* __restrict__ Xext, const float* __restrict__ W, int n) {
    const float* X = (K == 128) ? Xext : (const float*)g_x;
    __shared__ float Wsh[64][64];   // [k][col]  (cols accessed tx+16c: conflict-free)
    __shared__ float Xsh[64][65];   // [row][k]  padded
    int tid = threadIdx.x;
    int tx = tid & 15, ty = tid >> 4;
    int row0 = blockIdx.x * 64;
    float acc[4][4] = {};
    for (int kb = 0; kb < K; kb += 64) {
        for (int i = tid; i < 4096; i += 256) {
            int kk = i >> 6, c = i & 63;
            Wsh[kk][c] = W[(kb + kk) * 64 + c];
        }
        for (int i = tid; i < 4096; i += 256) {
            int r = i >> 6, kk = i & 63;
            int row = row0 + r;
            Xsh[r][kk] = (row < n) ? X[row * K + kb + kk] : 0.f;
        }
        __syncthreads();
#pragma unroll
        for (int k = 0; k < 64; k++) {
            float xv[4], wv[4];
#pragma unroll
            for (int r = 0; r < 4; r++) xv[r] = Xsh[ty + 16 * r][k];
#pragma unroll
            for (int c = 0; c < 4; c++) wv[c] = Wsh[k][tx + 16 * c];
#pragma unroll
            for (int r = 0; r < 4; r++)
#pragma unroll
                for (int c = 0; c < 4; c++) acc[r][c] = fmaf(xv[r], wv[c], acc[r][c]);
        }
        __syncthreads();
    }
#pragma unroll
    for (int r = 0; r < 4; r++) {
        int row = row0 + ty + 16 * r;
        if (row < n) {
#pragma unroll
            for (int c = 0; c < 4; c++) g_h[row * 64 + tx + 16 * c] = acc[r][c];
        }
    }
}

// ---------------- per-node attention dots: asrc/adst [N,2] ----------------
__global__ void att_kernel(const float* __restrict__ a_src, const float* __restrict__ a_dst, int n) {
    int w = (blockIdx.x * blockDim.x + threadIdx.x) >> 5;
    int lane = threadIdx.x & 31;
    if (w >= n) return;
    float v0 = g_h[w * 64 + lane];       // head0, c=lane
    float v1 = g_h[w * 64 + 32 + lane];  // head1
    float s0 = v0 * __ldg(a_src + lane);
    float s1 = v1 * __ldg(a_src + 32 + lane);
    float d0 = v0 * __ldg(a_dst + lane);
    float d1 = v1 * __ldg(a_dst + 32 + lane);
#pragma unroll
    for (int o = 16; o; o >>= 1) {
        s0 += __shfl_xor_sync(FULLMASK, s0, o);
        s1 += __shfl_xor_sync(FULLMASK, s1, o);
        d0 += __shfl_xor_sync(FULLMASK, d0, o);
        d1 += __shfl_xor_sync(FULLMASK, d1, o);
    }
    if (lane == 0) {
        g_asrc[w] = make_float2(s0, s1);
        g_adst[w] = make_float2(d0, d1);
    }
}

// ---------------- edge aggregation: one warp per dst node, online softmax ----------------
// lane owns channels {2*lane, 2*lane+1}; lanes 0-15 are head0, 16-31 head1.
template <bool FIRST>
__global__ void edge_agg(const float* __restrict__ bias, int n) {
    int w = (blockIdx.x * blockDim.x + threadIdx.x) >> 5;
    int lane = threadIdx.x & 31;
    if (w >= n) return;
    int beg = g_rowptr[w], end = g_rowptr[w + 1];
    float2 ad = g_adst[w];
    bool head0 = lane < 16;
    float m0 = -1e30f, m1 = -1e30f, s = 0.f;
    float2 acc = make_float2(0.f, 0.f);
    const float2* H2 = (const float2*)g_h;

    for (int base = beg; base < end; base += 32) {
        int j = base + lane;
        int src = 0;
        float e0 = -1e30f, e1 = -1e30f;
        if (j < end) {
            src = g_colsrc[j];
            float2 as = g_asrc[src];
            e0 = as.x + ad.x; e0 = e0 >= 0.f ? e0 : 0.2f * e0;
            e1 = as.y + ad.y; e1 = e1 >= 0.f ? e1 : 0.2f * e1;
        }
        // chunk max (both heads), all lanes get result
        float c0 = e0, c1 = e1;
#pragma unroll
        for (int o = 16; o; o >>= 1) {
            c0 = fmaxf(c0, __shfl_xor_sync(FULLMASK, c0, o));
            c1 = fmaxf(c1, __shfl_xor_sync(FULLMASK, c1, o));
        }
        float nm0 = fmaxf(m0, c0), nm1 = fmaxf(m1, c1);
        float sc = __expf(head0 ? m0 - nm0 : m1 - nm1);  // exp(-1e30)=0 on first chunk
        s *= sc; acc.x *= sc; acc.y *= sc;
        m0 = nm0; m1 = nm1;
        float mym = head0 ? nm0 : nm1;

        int cnt = min(32, end - base);
        for (int t = 0; t < cnt; t++) {
            int st = __shfl_sync(FULLMASK, src, t);
            float e0t = __shfl_sync(FULLMASK, e0, t);
            float e1t = __shfl_sync(FULLMASK, e1, t);
            float p = __expf((head0 ? e0t : e1t) - mym);
            s += p;
            float2 hv = H2[st * 32 + lane];  // coalesced 256B row gather (L2-resident)
            acc.x = fmaf(p, hv.x, acc.x);
            acc.y = fmaf(p, hv.y, acc.y);
        }
    }
    float inv = 1.0f / s;
    float2 b = ((const float2*)bias)[lane];
    float ox = acc.x * inv + b.x;
    float oy = acc.y * inv + b.y;
    if (FIRST) {
        ((float2*)g_init)[w * 32 + lane] = make_float2(ox, oy);  // initial_x (pre-elu)
    } else {
        float2 rv = ((const float2*)g_init)[w * 32 + lane];
        ox += rv.x; oy += rv.y;
    }
    // elu
    ox = ox > 0.f ? ox : __expf(ox) - 1.f;
    oy = oy > 0.f ? oy : __expf(oy) - 1.f;
    ((float2*)g_x)[w * 32 + lane] = make_float2(ox, oy);
}

// ---------------- output layer: hout = x @ W_out (64 -> 1), warp per node ----------------
__global__ void gemm_out(const float* __restrict__ Wout, int n) {
    int w = (blockIdx.x * blockDim.x + threadIdx.x) >> 5;
    int lane = threadIdx.x & 31;
    if (w >= n) return;
    float v = g_x[w * 64 + lane] * __ldg(Wout + lane) +
              g_x[w * 64 + 32 + lane] * __ldg(Wout + 32 + lane);
#pragma unroll
    for (int o = 16; o; o >>= 1) v += __shfl_xor_sync(FULLMASK, v, o);
    if (lane == 0) g_hout[w] = v;
}

__global__ void edge_out(const float* __restrict__ a_s, const float* __restrict__ a_d,
                         const float* __restrict__ b, float* __restrict__ out, int n) {
    int w = (blockIdx.x * blockDim.x + threadIdx.x) >> 5;
    int lane = threadIdx.x & 31;
    if (w >= n) return;
    int beg = g_rowptr[w], end = g_rowptr[w + 1];
    float asv = __ldg(a_s), adv = __ldg(a_d);
    float adT = g_hout[w] * adv;
    float m = -1e30f;
    for (int j = beg + lane; j < end; j += 32) {
        float hs = g_hout[g_colsrc[j]];
        float e = fmaf(hs, asv, adT);
        e = e >= 0.f ? e : 0.2f * e;
        m = fmaxf(m, e);
    }
#pragma unroll
    for (int o = 16; o; o >>= 1) m = fmaxf(m, __shfl_xor_sync(FULLMASK, m, o));
    float s = 0.f, accv = 0.f;
    for (int j = beg + lane; j < end; j += 32) {
        float hs = g_hout[g_colsrc[j]];
        float e = fmaf(hs, asv, adT);
        e = e >= 0.f ? e : 0.2f * e;
        float p = __expf(e - m);
        s += p;
        accv = fmaf(p, hs, accv);
    }
#pragma unroll
    for (int o = 16; o; o >>= 1) {
        s += __shfl_xor_sync(FULLMASK, s, o);
        accv += __shfl_xor_sync(FULLMASK, accv, o);
    }
    if (lane == 0) {
        float v = accv / s + __ldg(b);
        out[w] = 1.f / (1.f + __expf(-v));
    }
}

// ---------------- launcher ----------------
extern "C" void kernel_launch(void* const* d_in, const int* in_sizes, int n_in,
                              void* d_out, int out_size) {
    const float* node_attrs = (const float*)d_in[0];
    const int*   edge_index = (const int*)d_in[1];
    const float* W_in      = (const float*)d_in[2];
    const float* a_src_in  = (const float*)d_in[3];
    const float* a_dst_in  = (const float*)d_in[4];
    const float* b_in      = (const float*)d_in[5];
    const float* W_mid     = (const float*)d_in[6];
    const float* a_src_mid = (const float*)d_in[7];
    const float* a_dst_mid = (const float*)d_in[8];
    const float* b_mid     = (const float*)d_in[9];
    const float* W_out     = (const float*)d_in[10];
    const float* a_src_out = (const float*)d_in[11];
    const float* a_dst_out = (const float*)d_in[12];
    const float* b_out     = (const float*)d_in[13];
    float* out = (float*)d_out;

    int n = in_sizes[0] / 128;
    int e = in_sizes[1] / 2;

    const int tb = 256;
    // CSR build (graph identical for all layers)
    init_cnt<<<(n + tb - 1) / tb, tb>>>(n);
    hist<<<(e + tb - 1) / tb, tb>>>(edge_index, e);
    int nb = (n + SCAN_B - 1) / SCAN_B;
    scan1<<<nb, SCAN_B>>>(n);
    scan2<<<1, SCAN_B>>>(nb);
    scan3<<<nb, SCAN_B>>>(n, e + n);
    scatter<<<(e + n + tb - 1) / tb, tb>>>(edge_index, e, n);

    int gblocks = (n + 63) / 64;
    int wblocks = (n + 7) / 8;  // 8 warps per 256-thread block

    // input conv
    gemm_tile<128><<<gblocks, 256>>>(node_attrs, W_in, n);
    att_kernel<<<wblocks, 256>>>(a_src_in, a_dst_in, n);
    edge_agg<true><<<wblocks, 256>>>(b_in, n);

    // 6 mid convs (shared weights), residual from g_init
    for (int l = 0; l < 6; l++) {
        gemm_tile<64><<<gblocks, 256>>>(nullptr, W_mid, n);
        att_kernel<<<wblocks, 256>>>(a_src_mid, a_dst_mid, n);
        edge_agg<false><<<wblocks, 256>>>(b_mid, n);
    }

    // output conv + sigmoid
    gemm_out<<<wblocks, 256>>>(W_out, n);
    edge_out<<<wblocks, 256>>>(a_src_out, a_dst_out, b_out, out, n);
}

// round 4
// speedup vs baseline: 1.2718x; 1.2718x over previous
#include <cuda_runtime.h>

#define NMAX 100000
#define EMAX 1600000
#define FULLMASK 0xffffffffu
#define SCAN_B 1024

// ---------------- scratch (static device globals; no allocation) ----------------
__device__ float  g_h[NMAX * 64];       // h = x @ W for current layer
__device__ float  g_x[NMAX * 64];       // current layer input (post-elu)
__device__ float  g_init[NMAX * 64];    // initial_x (pre-elu output of first conv)
__device__ float2 g_asrc[NMAX];         // per-node attention dot, src side (2 heads)
__device__ float2 g_adst[NMAX];         // per-node attention dot, dst side (2 heads)
__device__ float2 g_p[EMAX + NMAX];     // per-edge unnormalized softmax weights (2 heads)
__device__ float2 g_invs[NMAX];         // per-node 1/sum (2 heads)
__device__ int    g_cnt[NMAX];
__device__ int    g_rowptr[NMAX + 1];
__device__ int    g_cursor[NMAX];
__device__ int    g_colsrc[EMAX + NMAX];
__device__ float  g_hout[NMAX];
__device__ int    g_bsums[1024];

// ---------------- CSR build (by destination node) ----------------
__global__ void init_cnt(int n) {
    int i = blockIdx.x * blockDim.x + threadIdx.x;
    if (i < n) g_cnt[i] = 1;  // self loop
}

__global__ void hist(const int* __restrict__ ei, int e) {
    int i = blockIdx.x * blockDim.x + threadIdx.x;
    if (i < e) atomicAdd(&g_cnt[ei[e + i]], 1);
}

__global__ void scan1(int n) {
    __shared__ int sh[SCAN_B];
    int i = blockIdx.x * SCAN_B + threadIdx.x;
    int v = (i < n) ? g_cnt[i] : 0;
    sh[threadIdx.x] = v;
    __syncthreads();
    for (int off = 1; off < SCAN_B; off <<= 1) {
        int t = (threadIdx.x >= off) ? sh[threadIdx.x - off] : 0;
        __syncthreads();
        sh[threadIdx.x] += t;
        __syncthreads();
    }
    if (i < n) g_rowptr[i] = sh[threadIdx.x] - v;  // exclusive
    if (threadIdx.x == SCAN_B - 1) g_bsums[blockIdx.x] = sh[threadIdx.x];
}

__global__ void scan2(int nb) {
    __shared__ int sh[SCAN_B];
    int v = (threadIdx.x < nb) ? g_bsums[threadIdx.x] : 0;
    sh[threadIdx.x] = v;
    __syncthreads();
    for (int off = 1; off < SCAN_B; off <<= 1) {
        int t = (threadIdx.x >= off) ? sh[threadIdx.x - off] : 0;
        __syncthreads();
        sh[threadIdx.x] += t;
        __syncthreads();
    }
    if (threadIdx.x < nb) g_bsums[threadIdx.x] = sh[threadIdx.x] - v;  // exclusive
}

__global__ void scan3(int n, int total) {
    int i = blockIdx.x * SCAN_B + threadIdx.x;
    if (i < n) {
        int v = g_rowptr[i] + g_bsums[blockIdx.x];
        g_rowptr[i] = v;
        g_cursor[i] = v;
    }
    if (i == 0) g_rowptr[n] = total;
}

__global__ void scatter(const int* __restrict__ ei, int e, int n) {
    int i = blockIdx.x * blockDim.x + threadIdx.x;
    if (i < e) {
        int src = ei[i];
        int dst = ei[e + i];
        int pos = atomicAdd(&g_cursor[dst], 1);
        g_colsrc[pos] = src;
    } else if (i < e + n) {
        int v = i - e;  // self loop
        int pos = atomicAdd(&g_cursor[v], 1);
        g_colsrc[pos] = v;
    }
}

// ---------------- GEMM: h = X @ W   (X:[n,K], W:[K,64] row-major) ----------------
// 64x64 block tile, 128 threads (16x8), 8x4 register micro-tile.
// rows = 8*ty + r (contiguous), cols = tx + 16*c (strided -> conflict-free Wsh reads? we
// instead use cols = 4*tx + c contiguous so W loads vectorize as LDS.128).
template <int K>
__global__ void gemm_tile(const float* __restrict__ Xext, const float* __restrict__ W, int n) {
    const float* X = (K == 128) ? Xext : (const float*)g_x;
    __shared__ float Xsh[64][65];   // [row][k] padded
    __shared__ float Wsh[64][64];   // [k][col]
    int tid = threadIdx.x;          // 128 threads
    int tx = tid & 15, ty = tid >> 4;  // tx: 0..15 (col group), ty: 0..7 (row group)
    int row0 = blockIdx.x * 64;
    float acc[8][4] = {};
    for (int kb = 0; kb < K; kb += 64) {
        // load W tile: 4096 floats via float4 (8 iters * 128 thr * 4)
        for (int i = tid; i < 1024; i += 128) {
            int kk = i >> 4, c4 = (i & 15) << 2;
            *(float4*)&Wsh[kk][c4] = *(const float4*)&W[(kb + kk) * 64 + c4];
        }
        // load X tile: float4 along k, coalesced along tid
        for (int i = tid; i < 1024; i += 128) {
            int k4 = (i & 15) << 2, r = i >> 4;
            int row = row0 + r;
            float4 v = (row < n) ? *(const float4*)&X[row * K + kb + k4]
                                 : make_float4(0.f, 0.f, 0.f, 0.f);
            Xsh[r][k4 + 0] = v.x; Xsh[r][k4 + 1] = v.y;
            Xsh[r][k4 + 2] = v.z; Xsh[r][k4 + 3] = v.w;
        }
        __syncthreads();
#pragma unroll 8
        for (int k = 0; k < 64; k++) {
            float4 wv = *(const float4*)&Wsh[k][tx << 2];  // LDS.128, no conflict
            float wc[4] = {wv.x, wv.y, wv.z, wv.w};
            float xr[8];
#pragma unroll
            for (int r = 0; r < 8; r++) xr[r] = Xsh[(ty << 3) + r][k];  // 2-addr broadcast
#pragma unroll
            for (int r = 0; r < 8; r++)
#pragma unroll
                for (int c = 0; c < 4; c++) acc[r][c] = fmaf(xr[r], wc[c], acc[r][c]);
        }
        __syncthreads();
    }
#pragma unroll
    for (int r = 0; r < 8; r++) {
        int row = row0 + (ty << 3) + r;
        if (row < n) {
            *(float4*)&g_h[row * 64 + (tx << 2)] =
                make_float4(acc[r][0], acc[r][1], acc[r][2], acc[r][3]);
        }
    }
}

// ---------------- per-node attention dots: asrc/adst [N,2] ----------------
__global__ void att_kernel(const float* __restrict__ a_src, const float* __restrict__ a_dst, int n) {
    int w = (blockIdx.x * blockDim.x + threadIdx.x) >> 5;
    int lane = threadIdx.x & 31;
    if (w >= n) return;
    float v0 = g_h[w * 64 + lane];       // head0
    float v1 = g_h[w * 64 + 32 + lane];  // head1
    float s0 = v0 * __ldg(a_src + lane);
    float s1 = v1 * __ldg(a_src + 32 + lane);
    float d0 = v0 * __ldg(a_dst + lane);
    float d1 = v1 * __ldg(a_dst + 32 + lane);
#pragma unroll
    for (int o = 16; o; o >>= 1) {
        s0 += __shfl_xor_sync(FULLMASK, s0, o);
        s1 += __shfl_xor_sync(FULLMASK, s1, o);
        d0 += __shfl_xor_sync(FULLMASK, d0, o);
        d1 += __shfl_xor_sync(FULLMASK, d1, o);
    }
    if (lane == 0) {
        g_asrc[w] = make_float2(s0, s1);
        g_adst[w] = make_float2(d0, d1);
    }
}

// ---------------- pass A: per-edge softmax weights (lane-parallel, warp per dst) ----------------
__global__ void edge_softmax(int n) {
    int w = (blockIdx.x * blockDim.x + threadIdx.x) >> 5;
    int lane = threadIdx.x & 31;
    if (w >= n) return;
    int beg = g_rowptr[w], end = g_rowptr[w + 1];
    float2 ad = g_adst[w];
    float m0 = -1e30f, m1 = -1e30f;
    for (int j = beg + lane; j < end; j += 32) {
        int src = g_colsrc[j];
        float2 as = g_asrc[src];
        float e0 = as.x + ad.x; e0 = e0 >= 0.f ? e0 : 0.2f * e0;
        float e1 = as.y + ad.y; e1 = e1 >= 0.f ? e1 : 0.2f * e1;
        g_p[j] = make_float2(e0, e1);
        m0 = fmaxf(m0, e0); m1 = fmaxf(m1, e1);
    }
#pragma unroll
    for (int o = 16; o; o >>= 1) {
        m0 = fmaxf(m0, __shfl_xor_sync(FULLMASK, m0, o));
        m1 = fmaxf(m1, __shfl_xor_sync(FULLMASK, m1, o));
    }
    float s0 = 0.f, s1 = 0.f;
    for (int j = beg + lane; j < end; j += 32) {
        float2 e = g_p[j];
        float p0 = __expf(e.x - m0), p1 = __expf(e.y - m1);
        s0 += p0; s1 += p1;
        g_p[j] = make_float2(p0, p1);
    }
#pragma unroll
    for (int o = 16; o; o >>= 1) {
        s0 += __shfl_xor_sync(FULLMASK, s0, o);
        s1 += __shfl_xor_sync(FULLMASK, s1, o);
    }
    if (lane == 0) g_invs[w] = make_float2(1.f / s0, 1.f / s1);
}

// ---------------- pass B: weighted gather (warp per dst, unrolled x4 for MLP) ----------------
// lane owns channels {2*lane, 2*lane+1}; lanes 0-15 head0, 16-31 head1.
template <bool FIRST>
__global__ void edge_agg(const float* __restrict__ bias, int n) {
    int w = (blockIdx.x * blockDim.x + threadIdx.x) >> 5;
    int lane = threadIdx.x & 31;
    if (w >= n) return;
    int beg = g_rowptr[w], end = g_rowptr[w + 1];
    bool head0 = lane < 16;
    float ax = 0.f, ay = 0.f;
    const float2* H2 = (const float2*)g_h;

    int j = beg;
    for (; j + 4 <= end; j += 4) {
        int s0 = g_colsrc[j], s1 = g_colsrc[j + 1], s2 = g_colsrc[j + 2], s3 = g_colsrc[j + 3];
        float2 q0 = g_p[j], q1 = g_p[j + 1], q2 = g_p[j + 2], q3 = g_p[j + 3];
        float2 h0 = __ldg(&H2[s0 * 32 + lane]);
        float2 h1 = __ldg(&H2[s1 * 32 + lane]);
        float2 h2 = __ldg(&H2[s2 * 32 + lane]);
        float2 h3 = __ldg(&H2[s3 * 32 + lane]);
        float w0 = head0 ? q0.x : q0.y;
        float w1 = head0 ? q1.x : q1.y;
        float w2 = head0 ? q2.x : q2.y;
        float w3 = head0 ? q3.x : q3.y;
        ax = fmaf(w0, h0.x, ax); ay = fmaf(w0, h0.y, ay);
        ax = fmaf(w1, h1.x, ax); ay = fmaf(w1, h1.y, ay);
        ax = fmaf(w2, h2.x, ax); ay = fmaf(w2, h2.y, ay);
        ax = fmaf(w3, h3.x, ax); ay = fmaf(w3, h3.y, ay);
    }
    for (; j < end; j++) {
        int s0 = g_colsrc[j];
        float2 q0 = g_p[j];
        float2 h0 = __ldg(&H2[s0 * 32 + lane]);
        float w0 = head0 ? q0.x : q0.y;
        ax = fmaf(w0, h0.x, ax); ay = fmaf(w0, h0.y, ay);
    }

    float2 iv2 = g_invs[w];
    float iv = head0 ? iv2.x : iv2.y;
    float2 b = __ldg(&((const float2*)bias)[lane]);
    float ox = ax * iv + b.x;
    float oy = ay * iv + b.y;
    if (FIRST) {
        ((float2*)g_init)[w * 32 + lane] = make_float2(ox, oy);  // initial_x (pre-elu)
    } else {
        float2 rv = ((const float2*)g_init)[w * 32 + lane];
        ox += rv.x; oy += rv.y;
    }
    // elu
    ox = ox > 0.f ? ox : __expf(ox) - 1.f;
    oy = oy > 0.f ? oy : __expf(oy) - 1.f;
    ((float2*)g_x)[w * 32 + lane] = make_float2(ox, oy);
}

// ---------------- output layer: hout = x @ W_out (64 -> 1), warp per node ----------------
__global__ void gemm_out(const float* __restrict__ Wout, int n) {
    int w = (blockIdx.x * blockDim.x + threadIdx.x) >> 5;
    int lane = threadIdx.x & 31;
    if (w >= n) return;
    float v = g_x[w * 64 + lane] * __ldg(Wout + lane) +
              g_x[w * 64 + 32 + lane] * __ldg(Wout + 32 + lane);
#pragma unroll
    for (int o = 16; o; o >>= 1) v += __shfl_xor_sync(FULLMASK, v, o);
    if (lane == 0) g_hout[w] = v;
}

__global__ void edge_out(const float* __restrict__ a_s, const float* __restrict__ a_d,
                         const float* __restrict__ b, float* __restrict__ out, int n) {
    int w = (blockIdx.x * blockDim.x + threadIdx.x) >> 5;
    int lane = threadIdx.x & 31;
    if (w >= n) return;
    int beg = g_rowptr[w], end = g_rowptr[w + 1];
    float asv = __ldg(a_s), adv = __ldg(a_d);
    float adT = g_hout[w] * adv;
    float m = -1e30f;
    for (int j = beg + lane; j < end; j += 32) {
        float hs = g_hout[g_colsrc[j]];
        float e = fmaf(hs, asv, adT);
        e = e >= 0.f ? e : 0.2f * e;
        m = fmaxf(m, e);
    }
#pragma unroll
    for (int o = 16; o; o >>= 1) m = fmaxf(m, __shfl_xor_sync(FULLMASK, m, o));
    float s = 0.f, accv = 0.f;
    for (int j = beg + lane; j < end; j += 32) {
        float hs = g_hout[g_colsrc[j]];
        float e = fmaf(hs, asv, adT);
        e = e >= 0.f ? e : 0.2f * e;
        float p = __expf(e - m);
        s += p;
        accv = fmaf(p, hs, accv);
    }
#pragma unroll
    for (int o = 16; o; o >>= 1) {
        s += __shfl_xor_sync(FULLMASK, s, o);
        accv += __shfl_xor_sync(FULLMASK, accv, o);
    }
    if (lane == 0) {
        float v = accv / s + __ldg(b);
        out[w] = 1.f / (1.f + __expf(-v));
    }
}

// ---------------- launcher ----------------
extern "C" void kernel_launch(void* const* d_in, const int* in_sizes, int n_in,
                              void* d_out, int out_size) {
    const float* node_attrs = (const float*)d_in[0];
    const int*   edge_index = (const int*)d_in[1];
    const float* W_in      = (const float*)d_in[2];
    const float* a_src_in  = (const float*)d_in[3];
    const float* a_dst_in  = (const float*)d_in[4];
    const float* b_in      = (const float*)d_in[5];
    const float* W_mid     = (const float*)d_in[6];
    const float* a_src_mid = (const float*)d_in[7];
    const float* a_dst_mid = (const float*)d_in[8];
    const float* b_mid     = (const float*)d_in[9];
    const float* W_out     = (const float*)d_in[10];
    const float* a_src_out = (const float*)d_in[11];
    const float* a_dst_out = (const float*)d_in[12];
    const float* b_out     = (const float*)d_in[13];
    float* out = (float*)d_out;

    int n = in_sizes[0] / 128;
    int e = in_sizes[1] / 2;

    const int tb = 256;
    // CSR build (graph identical for all layers)
    init_cnt<<<(n + tb - 1) / tb, tb>>>(n);
    hist<<<(e + tb - 1) / tb, tb>>>(edge_index, e);
    int nb = (n + SCAN_B - 1) / SCAN_B;
    scan1<<<nb, SCAN_B>>>(n);
    scan2<<<1, SCAN_B>>>(nb);
    scan3<<<nb, SCAN_B>>>(n, e + n);
    scatter<<<(e + n + tb - 1) / tb, tb>>>(edge_index, e, n);

    int gblocks = (n + 63) / 64;
    int wblocks = (n + 7) / 8;  // 8 warps per 256-thread block

    // input conv
    gemm_tile<128><<<gblocks, 128>>>(node_attrs, W_in, n);
    att_kernel<<<wblocks, 256>>>(a_src_in, a_dst_in, n);
    edge_softmax<<<wblocks, 256>>>(n);
    edge_agg<true><<<wblocks, 256>>>(b_in, n);

    // 6 mid convs (shared weights), residual from g_init
    for (int l = 0; l < 6; l++) {
        gemm_tile<64><<<gblocks, 128>>>(nullptr, W_mid, n);
        att_kernel<<<wblocks, 256>>>(a_src_mid, a_dst_mid, n);
        edge_softmax<<<wblocks, 256>>>(n);
        edge_agg<false><<<wblocks, 256>>>(b_mid, n);
    }

    // output conv + sigmoid
    gemm_out<<<wblocks, 256>>>(W_out, n);
    edge_out<<<wblocks, 256>>>(a_src_out, a_dst_out, b_out, out, n);
}

// round 5
// speedup vs baseline: 1.5371x; 1.2086x over previous
#include <cuda_runtime.h>

#define NMAX 100000
#define EMAX 1600000
#define FULLMASK 0xffffffffu
#define SCAN_B 1024

// ---------------- scratch (static device globals; no allocation) ----------------
__device__ float  g_h[NMAX * 64];       // h = x @ W for current layer
__device__ float  g_x[NMAX * 64];       // current layer input (post-elu)
__device__ float  g_init[NMAX * 64];    // initial_x (pre-elu output of first conv)
__device__ float2 g_asrc[NMAX];         // per-node attention dot, src side (2 heads)
__device__ float2 g_adst[NMAX];         // per-node attention dot, dst side (2 heads)
__device__ int    g_cnt[NMAX];
__device__ int    g_rowptr[NMAX + 1];
__device__ int    g_cursor[NMAX];
__device__ int    g_colsrc[EMAX + NMAX];
__device__ float  g_hout[NMAX];
__device__ int    g_bsums[1024];

// ---------------- CSR build (by destination node) ----------------
__global__ void init_cnt(int n) {
    int i = blockIdx.x * blockDim.x + threadIdx.x;
    if (i < n) g_cnt[i] = 1;  // self loop
}

__global__ void hist(const int* __restrict__ ei, int e) {
    int i = blockIdx.x * blockDim.x + threadIdx.x;
    if (i < e) atomicAdd(&g_cnt[ei[e + i]], 1);
}

__global__ void scan1(int n) {
    __shared__ int sh[SCAN_B];
    int i = blockIdx.x * SCAN_B + threadIdx.x;
    int v = (i < n) ? g_cnt[i] : 0;
    sh[threadIdx.x] = v;
    __syncthreads();
    for (int off = 1; off < SCAN_B; off <<= 1) {
        int t = (threadIdx.x >= off) ? sh[threadIdx.x - off] : 0;
        __syncthreads();
        sh[threadIdx.x] += t;
        __syncthreads();
    }
    if (i < n) g_rowptr[i] = sh[threadIdx.x] - v;  // exclusive
    if (threadIdx.x == SCAN_B - 1) g_bsums[blockIdx.x] = sh[threadIdx.x];
}

__global__ void scan2(int nb) {
    __shared__ int sh[SCAN_B];
    int v = (threadIdx.x < nb) ? g_bsums[threadIdx.x] : 0;
    sh[threadIdx.x] = v;
    __syncthreads();
    for (int off = 1; off < SCAN_B; off <<= 1) {
        int t = (threadIdx.x >= off) ? sh[threadIdx.x - off] : 0;
        __syncthreads();
        sh[threadIdx.x] += t;
        __syncthreads();
    }
    if (threadIdx.x < nb) g_bsums[threadIdx.x] = sh[threadIdx.x] - v;  // exclusive
}

__global__ void scan3(int n, int total) {
    int i = blockIdx.x * SCAN_B + threadIdx.x;
    if (i < n) {
        int v = g_rowptr[i] + g_bsums[blockIdx.x];
        g_rowptr[i] = v;
        g_cursor[i] = v;
    }
    if (i == 0) g_rowptr[n] = total;
}

__global__ void scatter(const int* __restrict__ ei, int e, int n) {
    int i = blockIdx.x * blockDim.x + threadIdx.x;
    if (i < e) {
        int src = ei[i];
        int dst = ei[e + i];
        int pos = atomicAdd(&g_cursor[dst], 1);
        g_colsrc[pos] = src;
    } else if (i < e + n) {
        int v = i - e;  // self loop
        int pos = atomicAdd(&g_cursor[v], 1);
        g_colsrc[pos] = v;
    }
}

// ---------------- GEMM + attention-dot epilogue ----------------
// h = X @ W (X:[n,K], W:[K,64] row-major), then per-row dots with a_src/a_dst.
// 64x64 block tile, 128 threads (tx:0..15 col group, ty:0..7 row group), 8x4 micro-tile.
// Heads: cols 0-31 = head0 (tx 0-7), cols 32-63 = head1 (tx 8-15).
template <int K>
__global__ void gemm_att(const float* __restrict__ Xext, const float* __restrict__ W,
                         const float* __restrict__ a_src, const float* __restrict__ a_dst, int n) {
    const float* X = (K == 128) ? Xext : (const float*)g_x;
    __shared__ float Xsh[64][65];   // [row][k] padded
    __shared__ float Wsh[64][64];   // [k][col]
    int tid = threadIdx.x;
    int tx = tid & 15, ty = tid >> 4;
    int row0 = blockIdx.x * 64;
    float acc[8][4] = {};
    for (int kb = 0; kb < K; kb += 64) {
        for (int i = tid; i < 1024; i += 128) {
            int kk = i >> 4, c4 = (i & 15) << 2;
            *(float4*)&Wsh[kk][c4] = *(const float4*)&W[(kb + kk) * 64 + c4];
        }
        for (int i = tid; i < 1024; i += 128) {
            int k4 = (i & 15) << 2, r = i >> 4;
            int row = row0 + r;
            float4 v = (row < n) ? *(const float4*)&X[row * K + kb + k4]
                                 : make_float4(0.f, 0.f, 0.f, 0.f);
            Xsh[r][k4 + 0] = v.x; Xsh[r][k4 + 1] = v.y;
            Xsh[r][k4 + 2] = v.z; Xsh[r][k4 + 3] = v.w;
        }
        __syncthreads();
#pragma unroll 8
        for (int k = 0; k < 64; k++) {
            float4 wv = *(const float4*)&Wsh[k][tx << 2];
            float wc[4] = {wv.x, wv.y, wv.z, wv.w};
            float xr[8];
#pragma unroll
            for (int r = 0; r < 8; r++) xr[r] = Xsh[(ty << 3) + r][k];
#pragma unroll
            for (int r = 0; r < 8; r++)
#pragma unroll
                for (int c = 0; c < 4; c++) acc[r][c] = fmaf(xr[r], wc[c], acc[r][c]);
        }
        __syncthreads();
    }
    // attention vector slice for this thread's 4 columns
    float as[4], ad[4];
#pragma unroll
    for (int c = 0; c < 4; c++) {
        as[c] = __ldg(a_src + (tx << 2) + c);
        ad[c] = __ldg(a_dst + (tx << 2) + c);
    }
    int head = tx >> 3;  // 0 or 1
#pragma unroll
    for (int r = 0; r < 8; r++) {
        int row = row0 + (ty << 3) + r;
        if (row < n) {
            *(float4*)&g_h[row * 64 + (tx << 2)] =
                make_float4(acc[r][0], acc[r][1], acc[r][2], acc[r][3]);
        }
        float ps = 0.f, pd = 0.f;
#pragma unroll
        for (int c = 0; c < 4; c++) {
            ps = fmaf(acc[r][c], as[c], ps);
            pd = fmaf(acc[r][c], ad[c], pd);
        }
        // reduce across the 8-lane head group (tx bits 0..2 live in lane bits 0..2)
#pragma unroll
        for (int o = 4; o; o >>= 1) {
            ps += __shfl_xor_sync(FULLMASK, ps, o);
            pd += __shfl_xor_sync(FULLMASK, pd, o);
        }
        if (row < n && (tx & 7) == 0) {
            ((float*)g_asrc)[row * 2 + head] = ps;
            ((float*)g_adst)[row * 2 + head] = pd;
        }
    }
}

// ---------------- fused edge kernel: softmax + weighted gather ----------------
// One warp per dst node. Chunk of 128 edges: lane-parallel logits -> chunk max ->
// online rescale -> lane-parallel p into smem -> broadcast gather-FMA loop (MLP=4).
// lane owns channels {2*lane, 2*lane+1}; lanes 0-15 head0, 16-31 head1.
template <bool FIRST>
__global__ void edge_fused(const float* __restrict__ bias, int n) {
    __shared__ float2 sp[8][128];   // per-warp chunk softmax weights (both heads)
    __shared__ int    ss[8][128];   // per-warp chunk src indices
    int w = (blockIdx.x * blockDim.x + threadIdx.x) >> 5;
    int lane = threadIdx.x & 31;
    int wl = (threadIdx.x >> 5) & 7;
    if (w >= n) return;
    int beg = g_rowptr[w], end = g_rowptr[w + 1];
    float2 ad = g_adst[w];
    bool head0 = lane < 16;
    const float2* H2 = (const float2*)g_h;
    const float* pp = &sp[wl][0].x + (head0 ? 0 : 1);  // my head's p stream (stride 2)

    float m0 = -1e30f, m1 = -1e30f;
    float s0 = 0.f, s1 = 0.f;
    float ax = 0.f, ay = 0.f;

    for (int base = beg; base < end; base += 128) {
        int cnt = min(128, end - base);
        // phase 1: lane-parallel logits, chunk max
        float e0[4], e1[4];
        float cm0 = -1e30f, cm1 = -1e30f;
#pragma unroll
        for (int t = 0; t < 4; t++) {
            int j = base + lane + 32 * t;
            e0[t] = -1e30f; e1[t] = -1e30f;
            if (j < end) {
                int src = g_colsrc[j];
                ss[wl][lane + 32 * t] = src;
                float2 asv = g_asrc[src];
                float v0 = asv.x + ad.x; v0 = v0 >= 0.f ? v0 : 0.2f * v0;
                float v1 = asv.y + ad.y; v1 = v1 >= 0.f ? v1 : 0.2f * v1;
                e0[t] = v0; e1[t] = v1;
                cm0 = fmaxf(cm0, v0); cm1 = fmaxf(cm1, v1);
            }
        }
#pragma unroll
        for (int o = 16; o; o >>= 1) {
            cm0 = fmaxf(cm0, __shfl_xor_sync(FULLMASK, cm0, o));
            cm1 = fmaxf(cm1, __shfl_xor_sync(FULLMASK, cm1, o));
        }
        float nm0 = fmaxf(m0, cm0), nm1 = fmaxf(m1, cm1);
        float sc0 = __expf(m0 - nm0), sc1 = __expf(m1 - nm1);  // 0 on first chunk
        s0 *= sc0; s1 *= sc1;
        float mysc = head0 ? sc0 : sc1;
        ax *= mysc; ay *= mysc;
        m0 = nm0; m1 = nm1;
        // phase 2: p into smem, accumulate partial sums
#pragma unroll
        for (int t = 0; t < 4; t++) {
            int j = base + lane + 32 * t;
            if (j < end) {
                float p0 = __expf(e0[t] - m0);
                float p1 = __expf(e1[t] - m1);
                s0 += p0; s1 += p1;
                sp[wl][lane + 32 * t] = make_float2(p0, p1);
            }
        }
        __syncwarp();
        // phase 3: broadcast gather-FMA, unrolled x4 for MLP
        int t = 0;
        for (; t + 4 <= cnt; t += 4) {
            int i0 = ss[wl][t], i1 = ss[wl][t + 1], i2 = ss[wl][t + 2], i3 = ss[wl][t + 3];
            float p0 = pp[2 * t], p1 = pp[2 * (t + 1)], p2 = pp[2 * (t + 2)], p3 = pp[2 * (t + 3)];
            float2 h0 = __ldg(&H2[i0 * 32 + lane]);
            float2 h1 = __ldg(&H2[i1 * 32 + lane]);
            float2 h2 = __ldg(&H2[i2 * 32 + lane]);
            float2 h3 = __ldg(&H2[i3 * 32 + lane]);
            ax = fmaf(p0, h0.x, ax); ay = fmaf(p0, h0.y, ay);
            ax = fmaf(p1, h1.x, ax); ay = fmaf(p1, h1.y, ay);
            ax = fmaf(p2, h2.x, ax); ay = fmaf(p2, h2.y, ay);
            ax = fmaf(p3, h3.x, ax); ay = fmaf(p3, h3.y, ay);
        }
        for (; t < cnt; t++) {
            int i0 = ss[wl][t];
            float p0 = pp[2 * t];
            float2 h0 = __ldg(&H2[i0 * 32 + lane]);
            ax = fmaf(p0, h0.x, ax); ay = fmaf(p0, h0.y, ay);
        }
        __syncwarp();
    }
    // final sum reduction (each lane holds a partial of its own edges, uniformly rescaled)
#pragma unroll
    for (int o = 16; o; o >>= 1) {
        s0 += __shfl_xor_sync(FULLMASK, s0, o);
        s1 += __shfl_xor_sync(FULLMASK, s1, o);
    }
    float iv = 1.0f / (head0 ? s0 : s1);
    float2 b = __ldg(&((const float2*)bias)[lane]);
    float ox = ax * iv + b.x;
    float oy = ay * iv + b.y;
    if (FIRST) {
        ((float2*)g_init)[w * 32 + lane] = make_float2(ox, oy);  // initial_x (pre-elu)
    } else {
        float2 rv = ((const float2*)g_init)[w * 32 + lane];
        ox += rv.x; oy += rv.y;
    }
    ox = ox > 0.f ? ox : __expf(ox) - 1.f;
    oy = oy > 0.f ? oy : __expf(oy) - 1.f;
    ((float2*)g_x)[w * 32 + lane] = make_float2(ox, oy);
}

// ---------------- output layer: hout = x @ W_out (64 -> 1), warp per node ----------------
__global__ void gemm_out(const float* __restrict__ Wout, int n) {
    int w = (blockIdx.x * blockDim.x + threadIdx.x) >> 5;
    int lane = threadIdx.x & 31;
    if (w >= n) return;
    float v = g_x[w * 64 + lane] * __ldg(Wout + lane) +
              g_x[w * 64 + 32 + lane] * __ldg(Wout + 32 + lane);
#pragma unroll
    for (int o = 16; o; o >>= 1) v += __shfl_xor_sync(FULLMASK, v, o);
    if (lane == 0) g_hout[w] = v;
}

__global__ void edge_out(const float* __restrict__ a_s, const float* __restrict__ a_d,
                         const float* __restrict__ b, float* __restrict__ out, int n) {
    int w = (blockIdx.x * blockDim.x + threadIdx.x) >> 5;
    int lane = threadIdx.x & 31;
    if (w >= n) return;
    int beg = g_rowptr[w], end = g_rowptr[w + 1];
    float asv = __ldg(a_s), adv = __ldg(a_d);
    float adT = g_hout[w] * adv;
    float m = -1e30f;
    for (int j = beg + lane; j < end; j += 32) {
        float hs = g_hout[g_colsrc[j]];
        float e = fmaf(hs, asv, adT);
        e = e >= 0.f ? e : 0.2f * e;
        m = fmaxf(m, e);
    }
#pragma unroll
    for (int o = 16; o; o >>= 1) m = fmaxf(m, __shfl_xor_sync(FULLMASK, m, o));
    float s = 0.f, accv = 0.f;
    for (int j = beg + lane; j < end; j += 32) {
        float hs = g_hout[g_colsrc[j]];
        float e = fmaf(hs, asv, adT);
        e = e >= 0.f ? e : 0.2f * e;
        float p = __expf(e - m);
        s += p;
        accv = fmaf(p, hs, accv);
    }
#pragma unroll
    for (int o = 16; o; o >>= 1) {
        s += __shfl_xor_sync(FULLMASK, s, o);
        accv += __shfl_xor_sync(FULLMASK, accv, o);
    }
    if (lane == 0) {
        float v = accv / s + __ldg(b);
        out[w] = 1.f / (1.f + __expf(-v));
    }
}

// ---------------- launcher ----------------
extern "C" void kernel_launch(void* const* d_in, const int* in_sizes, int n_in,
                              void* d_out, int out_size) {
    const float* node_attrs = (const float*)d_in[0];
    const int*   edge_index = (const int*)d_in[1];
    const float* W_in      = (const float*)d_in[2];
    const float* a_src_in  = (const float*)d_in[3];
    const float* a_dst_in  = (const float*)d_in[4];
    const float* b_in      = (const float*)d_in[5];
    const float* W_mid     = (const float*)d_in[6];
    const float* a_src_mid = (const float*)d_in[7];
    const float* a_dst_mid = (const float*)d_in[8];
    const float* b_mid     = (const float*)d_in[9];
    const float* W_out     = (const float*)d_in[10];
    const float* a_src_out = (const float*)d_in[11];
    const float* a_dst_out = (const float*)d_in[12];
    const float* b_out     = (const float*)d_in[13];
    float* out = (float*)d_out;

    int n = in_sizes[0] / 128;
    int e = in_sizes[1] / 2;

    const int tb = 256;
    // CSR build (graph identical for all layers)
    init_cnt<<<(n + tb - 1) / tb, tb>>>(n);
    hist<<<(e + tb - 1) / tb, tb>>>(edge_index, e);
    int nb = (n + SCAN_B - 1) / SCAN_B;
    scan1<<<nb, SCAN_B>>>(n);
    scan2<<<1, SCAN_B>>>(nb);
    scan3<<<nb, SCAN_B>>>(n, e + n);
    scatter<<<(e + n + tb - 1) / tb, tb>>>(edge_index, e, n);

    int gblocks = (n + 63) / 64;
    int wblocks = (n + 7) / 8;  // 8 warps per 256-thread block

    // input conv
    gemm_att<128><<<gblocks, 128>>>(node_attrs, W_in, a_src_in, a_dst_in, n);
    edge_fused<true><<<wblocks, 256>>>(b_in, n);

    // 6 mid convs (shared weights), residual from g_init
    for (int l = 0; l < 6; l++) {
        gemm_att<64><<<gblocks, 128>>>(nullptr, W_mid, a_src_mid, a_dst_mid, n);
        edge_fused<false><<<wblocks, 256>>>(b_mid, n);
    }

    // output conv + sigmoid
    gemm_out<<<wblocks, 256>>>(W_out, n);
    edge_out<<<wblocks, 256>>>(a_src_out, a_dst_out, b_out, out, n);
}

// round 6
// speedup vs baseline: 1.6433x; 1.0691x over previous
#include <cuda_runtime.h>
#include <cuda_fp16.h>

#define NMAX 100000
#define EMAX 1600000
#define FULLMASK 0xffffffffu
#define SCAN_B 1024

// ---------------- scratch (static device globals; no allocation) ----------------
__device__ __half2 g_hh[NMAX * 32];     // h = x @ W, fp16 gather table (64 ch = 32 half2)
__device__ float  g_x[NMAX * 64];       // current layer input (post-elu)
__device__ float  g_init[NMAX * 64];    // initial_x (pre-elu output of first conv)
__device__ float2 g_asrc[NMAX];         // per-node attention dot, src side (2 heads)
__device__ float2 g_adst[NMAX];         // per-node attention dot, dst side (2 heads)
__device__ int    g_cnt[NMAX];
__device__ int    g_rowptr[NMAX + 1];
__device__ int    g_cursor[NMAX];
__device__ int    g_colsrc[EMAX + NMAX];
__device__ float  g_hout[NMAX];
__device__ int    g_bsums[1024];

// ---------------- CSR build (by destination node) ----------------
__global__ void init_cnt(int n) {
    int i = blockIdx.x * blockDim.x + threadIdx.x;
    if (i < n) g_cnt[i] = 1;  // self loop
}

__global__ void hist(const int* __restrict__ ei, int e) {
    int i = blockIdx.x * blockDim.x + threadIdx.x;
    if (i < e) atomicAdd(&g_cnt[ei[e + i]], 1);
}

__global__ void scan1(int n) {
    __shared__ int sh[SCAN_B];
    int i = blockIdx.x * SCAN_B + threadIdx.x;
    int v = (i < n) ? g_cnt[i] : 0;
    sh[threadIdx.x] = v;
    __syncthreads();
    for (int off = 1; off < SCAN_B; off <<= 1) {
        int t = (threadIdx.x >= off) ? sh[threadIdx.x - off] : 0;
        __syncthreads();
        sh[threadIdx.x] += t;
        __syncthreads();
    }
    if (i < n) g_rowptr[i] = sh[threadIdx.x] - v;  // exclusive
    if (threadIdx.x == SCAN_B - 1) g_bsums[blockIdx.x] = sh[threadIdx.x];
}

__global__ void scan2(int nb) {
    __shared__ int sh[SCAN_B];
    int v = (threadIdx.x < nb) ? g_bsums[threadIdx.x] : 0;
    sh[threadIdx.x] = v;
    __syncthreads();
    for (int off = 1; off < SCAN_B; off <<= 1) {
        int t = (threadIdx.x >= off) ? sh[threadIdx.x - off] : 0;
        __syncthreads();
        sh[threadIdx.x] += t;
        __syncthreads();
    }
    if (threadIdx.x < nb) g_bsums[threadIdx.x] = sh[threadIdx.x] - v;  // exclusive
}

__global__ void scan3(int n, int total) {
    int i = blockIdx.x * SCAN_B + threadIdx.x;
    if (i < n) {
        int v = g_rowptr[i] + g_bsums[blockIdx.x];
        g_rowptr[i] = v;
        g_cursor[i] = v;
    }
    if (i == 0) g_rowptr[n] = total;
}

__global__ void scatter(const int* __restrict__ ei, int e, int n) {
    int i = blockIdx.x * blockDim.x + threadIdx.x;
    if (i < e) {
        int src = ei[i];
        int dst = ei[e + i];
        int pos = atomicAdd(&g_cursor[dst], 1);
        g_colsrc[pos] = src;
    } else if (i < e + n) {
        int v = i - e;  // self loop
        int pos = atomicAdd(&g_cursor[v], 1);
        g_colsrc[pos] = v;
    }
}

// ---------------- GEMM + attention-dot epilogue ----------------
// h = X @ W (X:[n,K], W:[K,64] row-major); per-row dots with a_src/a_dst from fp32 acc;
// h stored to the fp16 gather table. 64x64 tile, 128 threads, 8x4 micro-tile.
// Heads: cols 0-31 = head0 (tx 0-7), cols 32-63 = head1 (tx 8-15).
template <int K>
__global__ void gemm_att(const float* __restrict__ Xext, const float* __restrict__ W,
                         const float* __restrict__ a_src, const float* __restrict__ a_dst, int n) {
    const float* X = (K == 128) ? Xext : (const float*)g_x;
    __shared__ float Xsh[64][65];   // [row][k] padded
    __shared__ float Wsh[64][64];   // [k][col]
    int tid = threadIdx.x;
    int tx = tid & 15, ty = tid >> 4;
    int row0 = blockIdx.x * 64;
    float acc[8][4] = {};
    for (int kb = 0; kb < K; kb += 64) {
        for (int i = tid; i < 1024; i += 128) {
            int kk = i >> 4, c4 = (i & 15) << 2;
            *(float4*)&Wsh[kk][c4] = *(const float4*)&W[(kb + kk) * 64 + c4];
        }
        for (int i = tid; i < 1024; i += 128) {
            int k4 = (i & 15) << 2, r = i >> 4;
            int row = row0 + r;
            float4 v = (row < n) ? *(const float4*)&X[row * K + kb + k4]
                                 : make_float4(0.f, 0.f, 0.f, 0.f);
            Xsh[r][k4 + 0] = v.x; Xsh[r][k4 + 1] = v.y;
            Xsh[r][k4 + 2] = v.z; Xsh[r][k4 + 3] = v.w;
        }
        __syncthreads();
#pragma unroll 8
        for (int k = 0; k < 64; k++) {
            float4 wv = *(const float4*)&Wsh[k][tx << 2];
            float wc[4] = {wv.x, wv.y, wv.z, wv.w};
            float xr[8];
#pragma unroll
            for (int r = 0; r < 8; r++) xr[r] = Xsh[(ty << 3) + r][k];
#pragma unroll
            for (int r = 0; r < 8; r++)
#pragma unroll
                for (int c = 0; c < 4; c++) acc[r][c] = fmaf(xr[r], wc[c], acc[r][c]);
        }
        __syncthreads();
    }
    // attention vector slice for this thread's 4 columns
    float as[4], ad[4];
#pragma unroll
    for (int c = 0; c < 4; c++) {
        as[c] = __ldg(a_src + (tx << 2) + c);
        ad[c] = __ldg(a_dst + (tx << 2) + c);
    }
    int head = tx >> 3;  // 0 or 1
#pragma unroll
    for (int r = 0; r < 8; r++) {
        int row = row0 + (ty << 3) + r;
        if (row < n) {
            // fp16 gather table: 2 half2 per thread (8B store)
            __half2 p0 = __floats2half2_rn(acc[r][0], acc[r][1]);
            __half2 p1 = __floats2half2_rn(acc[r][2], acc[r][3]);
            *(__half2*)&g_hh[row * 32 + (tx << 1)] = p0;
            *(__half2*)&g_hh[row * 32 + (tx << 1) + 1] = p1;
        }
        float ps = 0.f, pd = 0.f;
#pragma unroll
        for (int c = 0; c < 4; c++) {
            ps = fmaf(acc[r][c], as[c], ps);
            pd = fmaf(acc[r][c], ad[c], pd);
        }
        // reduce across the 8-lane head group (tx bits 0..2 live in lane bits 0..2)
#pragma unroll
        for (int o = 4; o; o >>= 1) {
            ps += __shfl_xor_sync(FULLMASK, ps, o);
            pd += __shfl_xor_sync(FULLMASK, pd, o);
        }
        if (row < n && (tx & 7) == 0) {
            ((float*)g_asrc)[row * 2 + head] = ps;
            ((float*)g_adst)[row * 2 + head] = pd;
        }
    }
}

// ---------------- fused edge kernel: softmax + weighted gather (fp16 h) ----------------
// One warp per dst node. Chunk of 128 edges: lane-parallel logits -> chunk max ->
// online rescale -> lane-parallel p into smem -> broadcast gather-FMA loop (MLP=8).
// lane owns channels {2*lane, 2*lane+1}; lanes 0-15 head0, 16-31 head1.
template <bool FIRST>
__global__ void edge_fused(const float* __restrict__ bias, int n) {
    __shared__ float2 sp[8][128];   // per-warp chunk softmax weights (both heads)
    __shared__ int    ss[8][128];   // per-warp chunk src indices
    int w = (blockIdx.x * blockDim.x + threadIdx.x) >> 5;
    int lane = threadIdx.x & 31;
    int wl = (threadIdx.x >> 5) & 7;
    if (w >= n) return;
    int beg = g_rowptr[w], end = g_rowptr[w + 1];
    float2 ad = g_adst[w];
    bool head0 = lane < 16;
    const __half2* H = (const __half2*)g_hh;
    const float* pp = &sp[wl][0].x + (head0 ? 0 : 1);  // my head's p stream (stride 2)

    float m0 = -1e30f, m1 = -1e30f;
    float s0 = 0.f, s1 = 0.f;
    float ax = 0.f, ay = 0.f;

    for (int base = beg; base < end; base += 128) {
        int cnt = min(128, end - base);
        // phase 1: lane-parallel logits, chunk max
        float e0[4], e1[4];
        float cm0 = -1e30f, cm1 = -1e30f;
#pragma unroll
        for (int t = 0; t < 4; t++) {
            int j = base + lane + 32 * t;
            e0[t] = -1e30f; e1[t] = -1e30f;
            if (j < end) {
                int src = g_colsrc[j];
                ss[wl][lane + 32 * t] = src;
                float2 asv = g_asrc[src];
                float v0 = asv.x + ad.x; v0 = v0 >= 0.f ? v0 : 0.2f * v0;
                float v1 = asv.y + ad.y; v1 = v1 >= 0.f ? v1 : 0.2f * v1;
                e0[t] = v0; e1[t] = v1;
                cm0 = fmaxf(cm0, v0); cm1 = fmaxf(cm1, v1);
            }
        }
#pragma unroll
        for (int o = 16; o; o >>= 1) {
            cm0 = fmaxf(cm0, __shfl_xor_sync(FULLMASK, cm0, o));
            cm1 = fmaxf(cm1, __shfl_xor_sync(FULLMASK, cm1, o));
        }
        float nm0 = fmaxf(m0, cm0), nm1 = fmaxf(m1, cm1);
        float sc0 = __expf(m0 - nm0), sc1 = __expf(m1 - nm1);  // 0 on first chunk
        s0 *= sc0; s1 *= sc1;
        float mysc = head0 ? sc0 : sc1;
        ax *= mysc; ay *= mysc;
        m0 = nm0; m1 = nm1;
        // phase 2: p into smem, accumulate partial sums
#pragma unroll
        for (int t = 0; t < 4; t++) {
            int j = base + lane + 32 * t;
            if (j < end) {
                float p0 = __expf(e0[t] - m0);
                float p1 = __expf(e1[t] - m1);
                s0 += p0; s1 += p1;
                sp[wl][lane + 32 * t] = make_float2(p0, p1);
            }
        }
        __syncwarp();
        // phase 3: broadcast gather-FMA, unrolled x8 for MLP
        int t = 0;
        for (; t + 8 <= cnt; t += 8) {
            int idx[8];
            float pv[8];
            __half2 hv[8];
#pragma unroll
            for (int u = 0; u < 8; u++) {
                idx[u] = ss[wl][t + u];
                pv[u] = pp[2 * (t + u)];
            }
#pragma unroll
            for (int u = 0; u < 8; u++) hv[u] = __ldg(&H[idx[u] * 32 + lane]);
#pragma unroll
            for (int u = 0; u < 8; u++) {
                float2 f = __half22float2(hv[u]);
                ax = fmaf(pv[u], f.x, ax);
                ay = fmaf(pv[u], f.y, ay);
            }
        }
        for (; t < cnt; t++) {
            int i0 = ss[wl][t];
            float p0 = pp[2 * t];
            float2 f = __half22float2(__ldg(&H[i0 * 32 + lane]));
            ax = fmaf(p0, f.x, ax); ay = fmaf(p0, f.y, ay);
        }
        __syncwarp();
    }
    // final sum reduction (each lane holds a partial of its own edges, uniformly rescaled)
#pragma unroll
    for (int o = 16; o; o >>= 1) {
        s0 += __shfl_xor_sync(FULLMASK, s0, o);
        s1 += __shfl_xor_sync(FULLMASK, s1, o);
    }
    float iv = 1.0f / (head0 ? s0 : s1);
    float2 b = __ldg(&((const float2*)bias)[lane]);
    float ox = ax * iv + b.x;
    float oy = ay * iv + b.y;
    if (FIRST) {
        ((float2*)g_init)[w * 32 + lane] = make_float2(ox, oy);  // initial_x (pre-elu)
    } else {
        float2 rv = ((const float2*)g_init)[w * 32 + lane];
        ox += rv.x; oy += rv.y;
    }
    ox = ox > 0.f ? ox : __expf(ox) - 1.f;
    oy = oy > 0.f ? oy : __expf(oy) - 1.f;
    ((float2*)g_x)[w * 32 + lane] = make_float2(ox, oy);
}

// ---------------- output layer: hout = x @ W_out (64 -> 1), warp per node ----------------
__global__ void gemm_out(const float* __restrict__ Wout, int n) {
    int w = (blockIdx.x * blockDim.x + threadIdx.x) >> 5;
    int lane = threadIdx.x & 31;
    if (w >= n) return;
    float v = g_x[w * 64 + lane] * __ldg(Wout + lane) +
              g_x[w * 64 + 32 + lane] * __ldg(Wout + 32 + lane);
#pragma unroll
    for (int o = 16; o; o >>= 1) v += __shfl_xor_sync(FULLMASK, v, o);
    if (lane == 0) g_hout[w] = v;
}

__global__ void edge_out(const float* __restrict__ a_s, const float* __restrict__ a_d,
                         const float* __restrict__ b, float* __restrict__ out, int n) {
    int w = (blockIdx.x * blockDim.x + threadIdx.x) >> 5;
    int lane = threadIdx.x & 31;
    if (w >= n) return;
    int beg = g_rowptr[w], end = g_rowptr[w + 1];
    float asv = __ldg(a_s), adv = __ldg(a_d);
    float adT = g_hout[w] * adv;
    float m = -1e30f;
    for (int j = beg + lane; j < end; j += 32) {
        float hs = g_hout[g_colsrc[j]];
        float e = fmaf(hs, asv, adT);
        e = e >= 0.f ? e : 0.2f * e;
        m = fmaxf(m, e);
    }
#pragma unroll
    for (int o = 16; o; o >>= 1) m = fmaxf(m, __shfl_xor_sync(FULLMASK, m, o));
    float s = 0.f, accv = 0.f;
    for (int j = beg + lane; j < end; j += 32) {
        float hs = g_hout[g_colsrc[j]];
        float e = fmaf(hs, asv, adT);
        e = e >= 0.f ? e : 0.2f * e;
        float p = __expf(e - m);
        s += p;
        accv = fmaf(p, hs, accv);
    }
#pragma unroll
    for (int o = 16; o; o >>= 1) {
        s += __shfl_xor_sync(FULLMASK, s, o);
        accv += __shfl_xor_sync(FULLMASK, accv, o);
    }
    if (lane == 0) {
        float v = accv / s + __ldg(b);
        out[w] = 1.f / (1.f + __expf(-v));
    }
}

// ---------------- launcher ----------------
extern "C" void kernel_launch(void* const* d_in, const int* in_sizes, int n_in,
                              void* d_out, int out_size) {
    const float* node_attrs = (const float*)d_in[0];
    const int*   edge_index = (const int*)d_in[1];
    const float* W_in      = (const float*)d_in[2];
    const float* a_src_in  = (const float*)d_in[3];
    const float* a_dst_in  = (const float*)d_in[4];
    const float* b_in      = (const float*)d_in[5];
    const float* W_mid     = (const float*)d_in[6];
    const float* a_src_mid = (const float*)d_in[7];
    const float* a_dst_mid = (const float*)d_in[8];
    const float* b_mid     = (const float*)d_in[9];
    const float* W_out     = (const float*)d_in[10];
    const float* a_src_out = (const float*)d_in[11];
    const float* a_dst_out = (const float*)d_in[12];
    const float* b_out     = (const float*)d_in[13];
    float* out = (float*)d_out;

    int n = in_sizes[0] / 128;
    int e = in_sizes[1] / 2;

    const int tb = 256;
    // CSR build (graph identical for all layers)
    init_cnt<<<(n + tb - 1) / tb, tb>>>(n);
    hist<<<(e + tb - 1) / tb, tb>>>(edge_index, e);
    int nb = (n + SCAN_B - 1) / SCAN_B;
    scan1<<<nb, SCAN_B>>>(n);
    scan2<<<1, SCAN_B>>>(nb);
    scan3<<<nb, SCAN_B>>>(n, e + n);
    scatter<<<(e + n + tb - 1) / tb, tb>>>(edge_index, e, n);

    int gblocks = (n + 63) / 64;
    int wblocks = (n + 7) / 8;  // 8 warps per 256-thread block

    // input conv
    gemm_att<128><<<gblocks, 128>>>(node_attrs, W_in, a_src_in, a_dst_in, n);
    edge_fused<true><<<wblocks, 256>>>(b_in, n);

    // 6 mid convs (shared weights), residual from g_init
    for (int l = 0; l < 6; l++) {
        gemm_att<64><<<gblocks, 128>>>(nullptr, W_mid, a_src_mid, a_dst_mid, n);
        edge_fused<false><<<wblocks, 256>>>(b_mid, n);
    }

    // output conv + sigmoid
    gemm_out<<<wblocks, 256>>>(W_out, n);
    edge_out<<<wblocks, 256>>>(a_src_out, a_dst_out, b_out, out, n);
}

// round 7
// speedup vs baseline: 1.6506x; 1.0044x over previous
#include <cuda_runtime.h>
#include <cuda_fp16.h>

#define NMAX 100000
#define EMAX 1600000
#define FULLMASK 0xffffffffu
#define SCAN_B 1024

// ---------------- scratch (static device globals; no allocation) ----------------
__device__ __half2 g_hh[NMAX * 32];     // h = x @ W, fp16 gather table (64 ch = 32 half2)
__device__ float  g_x[NMAX * 64];       // current layer input (post-elu)
__device__ float  g_init[NMAX * 64];    // initial_x (pre-elu output of first conv)
__device__ float2 g_asrc[NMAX];         // per-node attention dot, src side (2 heads)
__device__ float2 g_adst[NMAX];         // per-node attention dot, dst side (2 heads)
__device__ int    g_cnt[NMAX];
__device__ int    g_rowptr[NMAX + 1];
__device__ int    g_cursor[NMAX];
__device__ int    g_colsrc[EMAX + NMAX];
__device__ float  g_hout[NMAX];
__device__ int    g_bsums[1024];

// ---------------- CSR build (by destination node) ----------------
__global__ void init_cnt(int n) {
    int i = blockIdx.x * blockDim.x + threadIdx.x;
    if (i < n) g_cnt[i] = 1;  // self loop
}

__global__ void hist(const int* __restrict__ ei, int e) {
    int i = blockIdx.x * blockDim.x + threadIdx.x;
    if (i < e) atomicAdd(&g_cnt[ei[e + i]], 1);
}

__global__ void scan1(int n) {
    __shared__ int sh[SCAN_B];
    int i = blockIdx.x * SCAN_B + threadIdx.x;
    int v = (i < n) ? g_cnt[i] : 0;
    sh[threadIdx.x] = v;
    __syncthreads();
    for (int off = 1; off < SCAN_B; off <<= 1) {
        int t = (threadIdx.x >= off) ? sh[threadIdx.x - off] : 0;
        __syncthreads();
        sh[threadIdx.x] += t;
        __syncthreads();
    }
    if (i < n) g_rowptr[i] = sh[threadIdx.x] - v;  // exclusive
    if (threadIdx.x == SCAN_B - 1) g_bsums[blockIdx.x] = sh[threadIdx.x];
}

__global__ void scan2(int nb) {
    __shared__ int sh[SCAN_B];
    int v = (threadIdx.x < nb) ? g_bsums[threadIdx.x] : 0;
    sh[threadIdx.x] = v;
    __syncthreads();
    for (int off = 1; off < SCAN_B; off <<= 1) {
        int t = (threadIdx.x >= off) ? sh[threadIdx.x - off] : 0;
        __syncthreads();
        sh[threadIdx.x] += t;
        __syncthreads();
    }
    if (threadIdx.x < nb) g_bsums[threadIdx.x] = sh[threadIdx.x] - v;  // exclusive
}

__global__ void scan3(int n, int total) {
    int i = blockIdx.x * SCAN_B + threadIdx.x;
    if (i < n) {
        int v = g_rowptr[i] + g_bsums[blockIdx.x];
        g_rowptr[i] = v;
        g_cursor[i] = v;
    }
    if (i == 0) g_rowptr[n] = total;
}

__global__ void scatter(const int* __restrict__ ei, int e, int n) {
    int i = blockIdx.x * blockDim.x + threadIdx.x;
    if (i < e) {
        int src = ei[i];
        int dst = ei[e + i];
        int pos = atomicAdd(&g_cursor[dst], 1);
        g_colsrc[pos] = src;
    } else if (i < e + n) {
        int v = i - e;  // self loop
        int pos = atomicAdd(&g_cursor[v], 1);
        g_colsrc[pos] = v;
    }
}

// ---------------- GEMM + attention-dot epilogue ----------------
// h = X @ W (X:[n,K], W:[K,64] row-major); per-row dots with a_src/a_dst from fp32 acc;
// h stored to the fp16 gather table. 64x64 tile, 128 threads, 8x4 micro-tile.
// Heads: cols 0-31 = head0 (tx 0-7), cols 32-63 = head1 (tx 8-15).
template <int K>
__global__ void gemm_att(const float* __restrict__ Xext, const float* __restrict__ W,
                         const float* __restrict__ a_src, const float* __restrict__ a_dst, int n) {
    const float* X = (K == 128) ? Xext : (const float*)g_x;
    __shared__ float Xsh[64][65];   // [row][k] padded
    __shared__ float Wsh[64][64];   // [k][col]
    int tid = threadIdx.x;
    int tx = tid & 15, ty = tid >> 4;
    int row0 = blockIdx.x * 64;
    float acc[8][4] = {};
    for (int kb = 0; kb < K; kb += 64) {
        for (int i = tid; i < 1024; i += 128) {
            int kk = i >> 4, c4 = (i & 15) << 2;
            *(float4*)&Wsh[kk][c4] = *(const float4*)&W[(kb + kk) * 64 + c4];
        }
        for (int i = tid; i < 1024; i += 128) {
            int k4 = (i & 15) << 2, r = i >> 4;
            int row = row0 + r;
            float4 v = (row < n) ? *(const float4*)&X[row * K + kb + k4]
                                 : make_float4(0.f, 0.f, 0.f, 0.f);
            Xsh[r][k4 + 0] = v.x; Xsh[r][k4 + 1] = v.y;
            Xsh[r][k4 + 2] = v.z; Xsh[r][k4 + 3] = v.w;
        }
        __syncthreads();
#pragma unroll 8
        for (int k = 0; k < 64; k++) {
            float4 wv = *(const float4*)&Wsh[k][tx << 2];
            float wc[4] = {wv.x, wv.y, wv.z, wv.w};
            float xr[8];
#pragma unroll
            for (int r = 0; r < 8; r++) xr[r] = Xsh[(ty << 3) + r][k];
#pragma unroll
            for (int r = 0; r < 8; r++)
#pragma unroll
                for (int c = 0; c < 4; c++) acc[r][c] = fmaf(xr[r], wc[c], acc[r][c]);
        }
        __syncthreads();
    }
    // attention vector slice for this thread's 4 columns
    float as[4], ad[4];
#pragma unroll
    for (int c = 0; c < 4; c++) {
        as[c] = __ldg(a_src + (tx << 2) + c);
        ad[c] = __ldg(a_dst + (tx << 2) + c);
    }
    int head = tx >> 3;  // 0 or 1
#pragma unroll
    for (int r = 0; r < 8; r++) {
        int row = row0 + (ty << 3) + r;
        if (row < n) {
            // fp16 gather table: 2 half2 per thread (8B store)
            __half2 p0 = __floats2half2_rn(acc[r][0], acc[r][1]);
            __half2 p1 = __floats2half2_rn(acc[r][2], acc[r][3]);
            *(__half2*)&g_hh[row * 32 + (tx << 1)] = p0;
            *(__half2*)&g_hh[row * 32 + (tx << 1) + 1] = p1;
        }
        float ps = 0.f, pd = 0.f;
#pragma unroll
        for (int c = 0; c < 4; c++) {
            ps = fmaf(acc[r][c], as[c], ps);
            pd = fmaf(acc[r][c], ad[c], pd);
        }
        // reduce across the 8-lane head group (tx bits 0..2 live in lane bits 0..2)
#pragma unroll
        for (int o = 4; o; o >>= 1) {
            ps += __shfl_xor_sync(FULLMASK, ps, o);
            pd += __shfl_xor_sync(FULLMASK, pd, o);
        }
        if (row < n && (tx & 7) == 0) {
            ((float*)g_asrc)[row * 2 + head] = ps;
            ((float*)g_adst)[row * 2 + head] = pd;
        }
    }
}

// ---------------- fused edge kernel: softmax + weighted gather (fp16 h) ----------------
// One warp per dst node. Chunk of 128 edges: lane-parallel logits -> chunk max ->
// online rescale -> lane-parallel p into smem -> broadcast gather-FMA loop (MLP=8).
// lane owns channels {2*lane, 2*lane+1}; lanes 0-15 head0, 16-31 head1.
template <bool FIRST>
__global__ void edge_fused(const float* __restrict__ bias, int n) {
    __shared__ float2 sp[8][128];   // per-warp chunk softmax weights (both heads)
    __shared__ int    ss[8][128];   // per-warp chunk src indices
    int w = (blockIdx.x * blockDim.x + threadIdx.x) >> 5;
    int lane = threadIdx.x & 31;
    int wl = (threadIdx.x >> 5) & 7;
    if (w >= n) return;
    int beg = g_rowptr[w], end = g_rowptr[w + 1];
    float2 ad = g_adst[w];
    bool head0 = lane < 16;
    const __half2* H = (const __half2*)g_hh;
    const float* pp = &sp[wl][0].x + (head0 ? 0 : 1);  // my head's p stream (stride 2)

    float m0 = -1e30f, m1 = -1e30f;
    float s0 = 0.f, s1 = 0.f;
    float ax = 0.f, ay = 0.f;

    for (int base = beg; base < end; base += 128) {
        int cnt = min(128, end - base);
        // phase 1: lane-parallel logits, chunk max
        float e0[4], e1[4];
        float cm0 = -1e30f, cm1 = -1e30f;
#pragma unroll
        for (int t = 0; t < 4; t++) {
            int j = base + lane + 32 * t;
            e0[t] = -1e30f; e1[t] = -1e30f;
            if (j < end) {
                int src = g_colsrc[j];
                ss[wl][lane + 32 * t] = src;
                float2 asv = g_asrc[src];
                float v0 = asv.x + ad.x; v0 = v0 >= 0.f ? v0 : 0.2f * v0;
                float v1 = asv.y + ad.y; v1 = v1 >= 0.f ? v1 : 0.2f * v1;
                e0[t] = v0; e1[t] = v1;
                cm0 = fmaxf(cm0, v0); cm1 = fmaxf(cm1, v1);
            }
        }
#pragma unroll
        for (int o = 16; o; o >>= 1) {
            cm0 = fmaxf(cm0, __shfl_xor_sync(FULLMASK, cm0, o));
            cm1 = fmaxf(cm1, __shfl_xor_sync(FULLMASK, cm1, o));
        }
        float nm0 = fmaxf(m0, cm0), nm1 = fmaxf(m1, cm1);
        float sc0 = __expf(m0 - nm0), sc1 = __expf(m1 - nm1);  // 0 on first chunk
        s0 *= sc0; s1 *= sc1;
        float mysc = head0 ? sc0 : sc1;
        ax *= mysc; ay *= mysc;
        m0 = nm0; m1 = nm1;
        // phase 2: p into smem, accumulate partial sums
#pragma unroll
        for (int t = 0; t < 4; t++) {
            int j = base + lane + 32 * t;
            if (j < end) {
                float p0 = __expf(e0[t] - m0);
                float p1 = __expf(e1[t] - m1);
                s0 += p0; s1 += p1;
                sp[wl][lane + 32 * t] = make_float2(p0, p1);
            }
        }
        __syncwarp();
        // phase 3: broadcast gather-FMA, unrolled x8 for MLP
        int t = 0;
        for (; t + 8 <= cnt; t += 8) {
            int idx[8];
            float pv[8];
            __half2 hv[8];
#pragma unroll
            for (int u = 0; u < 8; u++) {
                idx[u] = ss[wl][t + u];
                pv[u] = pp[2 * (t + u)];
            }
#pragma unroll
            for (int u = 0; u < 8; u++) hv[u] = __ldg(&H[idx[u] * 32 + lane]);
#pragma unroll
            for (int u = 0; u < 8; u++) {
                float2 f = __half22float2(hv[u]);
                ax = fmaf(pv[u], f.x, ax);
                ay = fmaf(pv[u], f.y, ay);
            }
        }
        for (; t < cnt; t++) {
            int i0 = ss[wl][t];
            float p0 = pp[2 * t];
            float2 f = __half22float2(__ldg(&H[i0 * 32 + lane]));
            ax = fmaf(p0, f.x, ax); ay = fmaf(p0, f.y, ay);
        }
        __syncwarp();
    }
    // final sum reduction (each lane holds a partial of its own edges, uniformly rescaled)
#pragma unroll
    for (int o = 16; o; o >>= 1) {
        s0 += __shfl_xor_sync(FULLMASK, s0, o);
        s1 += __shfl_xor_sync(FULLMASK, s1, o);
    }
    float iv = 1.0f / (head0 ? s0 : s1);
    float2 b = __ldg(&((const float2*)bias)[lane]);
    float ox = ax * iv + b.x;
    float oy = ay * iv + b.y;
    if (FIRST) {
        ((float2*)g_init)[w * 32 + lane] = make_float2(ox, oy);  // initial_x (pre-elu)
    } else {
        float2 rv = ((const float2*)g_init)[w * 32 + lane];
        ox += rv.x; oy += rv.y;
    }
    ox = ox > 0.f ? ox : __expf(ox) - 1.f;
    oy = oy > 0.f ? oy : __expf(oy) - 1.f;
    ((float2*)g_x)[w * 32 + lane] = make_float2(ox, oy);
}

// ---------------- output layer: hout = x @ W_out (64 -> 1), warp per node ----------------
__global__ void gemm_out(const float* __restrict__ Wout, int n) {
    int w = (blockIdx.x * blockDim.x + threadIdx.x) >> 5;
    int lane = threadIdx.x & 31;
    if (w >= n) return;
    float v = g_x[w * 64 + lane] * __ldg(Wout + lane) +
              g_x[w * 64 + 32 + lane] * __ldg(Wout + 32 + lane);
#pragma unroll
    for (int o = 16; o; o >>= 1) v += __shfl_xor_sync(FULLMASK, v, o);
    if (lane == 0) g_hout[w] = v;
}

__global__ void edge_out(const float* __restrict__ a_s, const float* __restrict__ a_d,
                         const float* __restrict__ b, float* __restrict__ out, int n) {
    int w = (blockIdx.x * blockDim.x + threadIdx.x) >> 5;
    int lane = threadIdx.x & 31;
    if (w >= n) return;
    int beg = g_rowptr[w], end = g_rowptr[w + 1];
    float asv = __ldg(a_s), adv = __ldg(a_d);
    float adT = g_hout[w] * adv;
    float m = -1e30f;
    for (int j = beg + lane; j < end; j += 32) {
        float hs = g_hout[g_colsrc[j]];
        float e = fmaf(hs, asv, adT);
        e = e >= 0.f ? e : 0.2f * e;
        m = fmaxf(m, e);
    }
#pragma unroll
    for (int o = 16; o; o >>= 1) m = fmaxf(m, __shfl_xor_sync(FULLMASK, m, o));
    float s = 0.f, accv = 0.f;
    for (int j = beg + lane; j < end; j += 32) {
        float hs = g_hout[g_colsrc[j]];
        float e = fmaf(hs, asv, adT);
        e = e >= 0.f ? e : 0.2f * e;
        float p = __expf(e - m);
        s += p;
        accv = fmaf(p, hs, accv);
    }
#pragma unroll
    for (int o = 16; o; o >>= 1) {
        s += __shfl_xor_sync(FULLMASK, s, o);
        accv += __shfl_xor_sync(FULLMASK, accv, o);
    }
    if (lane == 0) {
        float v = accv / s + __ldg(b);
        out[w] = 1.f / (1.f + __expf(-v));
    }
}

// ---------------- launcher ----------------
extern "C" void kernel_launch(void* const* d_in, const int* in_sizes, int n_in,
                              void* d_out, int out_size) {
    const float* node_attrs = (const float*)d_in[0];
    const int*   edge_index = (const int*)d_in[1];
    const float* W_in      = (const float*)d_in[2];
    const float* a_src_in  = (const float*)d_in[3];
    const float* a_dst_in  = (const float*)d_in[4];
    const float* b_in      = (const float*)d_in[5];
    const float* W_mid     = (const float*)d_in[6];
    const float* a_src_mid = (const float*)d_in[7];
    const float* a_dst_mid = (const float*)d_in[8];
    const float* b_mid     = (const float*)d_in[9];
    const float* W_out     = (const float*)d_in[10];
    const float* a_src_out = (const float*)d_in[11];
    const float* a_dst_out = (const float*)d_in[12];
    const float* b_out     = (const float*)d_in[13];
    float* out = (float*)d_out;

    int n = in_sizes[0] / 128;
    int e = in_sizes[1] / 2;

    const int tb = 256;
    // CSR build (graph identical for all layers)
    init_cnt<<<(n + tb - 1) / tb, tb>>>(n);
    hist<<<(e + tb - 1) / tb, tb>>>(edge_index, e);
    int nb = (n + SCAN_B - 1) / SCAN_B;
    scan1<<<nb, SCAN_B>>>(n);
    scan2<<<1, SCAN_B>>>(nb);
    scan3<<<nb, SCAN_B>>>(n, e + n);
    scatter<<<(e + n + tb - 1) / tb, tb>>>(edge_index, e, n);

    int gblocks = (n + 63) / 64;
    int wblocks = (n + 7) / 8;  // 8 warps per 256-thread block

    // input conv
    gemm_att<128><<<gblocks, 128>>>(node_attrs, W_in, a_src_in, a_dst_in, n);
    edge_fused<true><<<wblocks, 256>>>(b_in, n);

    // 6 mid convs (shared weights), residual from g_init
    for (int l = 0; l < 6; l++) {
        gemm_att<64><<<gblocks, 128>>>(nullptr, W_mid, a_src_mid, a_dst_mid, n);
        edge_fused<false><<<wblocks, 256>>>(b_mid, n);
    }

    // output conv + sigmoid
    gemm_out<<<wblocks, 256>>>(W_out, n);
    edge_out<<<wblocks, 256>>>(a_src_out, a_dst_out, b_out, out, n);
}

// round 8
// speedup vs baseline: 1.6825x; 1.0193x over previous
#include <cuda_runtime.h>
#include <cuda_fp16.h>

#define NMAX 100000
#define EMAX 1600000
#define FULLMASK 0xffffffffu
#define SCAN_B 1024

// ---------------- scratch (static device globals; no allocation) ----------------
__device__ __half2 g_hh[NMAX * 32];     // h = x @ W, fp16 gather table (64 ch = 32 half2)
__device__ float  g_x[NMAX * 64];       // current layer input (post-elu)
__device__ float  g_init[NMAX * 64];    // initial_x (pre-elu output of first conv)
__device__ float2 g_asrc[NMAX];         // per-node attention dot, src side (2 heads)
__device__ float2 g_adst[NMAX];         // per-node attention dot, dst side (2 heads)
__device__ int    g_cnt[NMAX];
__device__ int    g_rowptr[NMAX + 1];
__device__ int    g_cursor[NMAX];
__device__ int    g_colsrc[EMAX + NMAX];
__device__ float  g_hout[NMAX];
__device__ int    g_bsums[1024];

// ---------------- CSR build (by destination node) ----------------
__global__ void init_cnt(int n) {
    int i = blockIdx.x * blockDim.x + threadIdx.x;
    if (i < n) g_cnt[i] = 1;  // self loop
}

__global__ void hist(const int* __restrict__ ei, int e) {
    int i = blockIdx.x * blockDim.x + threadIdx.x;
    if (i < e) atomicAdd(&g_cnt[ei[e + i]], 1);
}

__global__ void scan1(int n) {
    __shared__ int sh[SCAN_B];
    int i = blockIdx.x * SCAN_B + threadIdx.x;
    int v = (i < n) ? g_cnt[i] : 0;
    sh[threadIdx.x] = v;
    __syncthreads();
    for (int off = 1; off < SCAN_B; off <<= 1) {
        int t = (threadIdx.x >= off) ? sh[threadIdx.x - off] : 0;
        __syncthreads();
        sh[threadIdx.x] += t;
        __syncthreads();
    }
    if (i < n) g_rowptr[i] = sh[threadIdx.x] - v;  // exclusive
    if (threadIdx.x == SCAN_B - 1) g_bsums[blockIdx.x] = sh[threadIdx.x];
}

__global__ void scan2(int nb) {
    __shared__ int sh[SCAN_B];
    int v = (threadIdx.x < nb) ? g_bsums[threadIdx.x] : 0;
    sh[threadIdx.x] = v;
    __syncthreads();
    for (int off = 1; off < SCAN_B; off <<= 1) {
        int t = (threadIdx.x >= off) ? sh[threadIdx.x - off] : 0;
        __syncthreads();
        sh[threadIdx.x] += t;
        __syncthreads();
    }
    if (threadIdx.x < nb) g_bsums[threadIdx.x] = sh[threadIdx.x] - v;  // exclusive
}

__global__ void scan3(int n, int total) {
    int i = blockIdx.x * SCAN_B + threadIdx.x;
    if (i < n) {
        int v = g_rowptr[i] + g_bsums[blockIdx.x];
        g_rowptr[i] = v;
        g_cursor[i] = v;
    }
    if (i == 0) g_rowptr[n] = total;
}

__global__ void scatter(const int* __restrict__ ei, int e, int n) {
    int i = blockIdx.x * blockDim.x + threadIdx.x;
    if (i < e) {
        int src = ei[i];
        int dst = ei[e + i];
        int pos = atomicAdd(&g_cursor[dst], 1);
        g_colsrc[pos] = src;
    } else if (i < e + n) {
        int v = i - e;  // self loop
        int pos = atomicAdd(&g_cursor[v], 1);
        g_colsrc[pos] = v;
    }
}

// ---------------- GEMM + attention-dot epilogue ----------------
// h = X @ W (X:[n,K], W:[K,64] row-major); per-row dots with a_src/a_dst from fp32 acc;
// h stored to the fp16 gather table. 64x64 tile, 128 threads, 8x4 micro-tile.
// Heads: cols 0-31 = head0 (tx 0-7), cols 32-63 = head1 (tx 8-15).
template <int K>
__global__ void gemm_att(const float* __restrict__ Xext, const float* __restrict__ W,
                         const float* __restrict__ a_src, const float* __restrict__ a_dst, int n) {
    const float* X = (K == 128) ? Xext : (const float*)g_x;
    __shared__ float Xsh[64][65];   // [row][k] padded
    __shared__ float Wsh[64][64];   // [k][col]
    int tid = threadIdx.x;
    int tx = tid & 15, ty = tid >> 4;
    int row0 = blockIdx.x * 64;
    float acc[8][4] = {};
    for (int kb = 0; kb < K; kb += 64) {
        for (int i = tid; i < 1024; i += 128) {
            int kk = i >> 4, c4 = (i & 15) << 2;
            *(float4*)&Wsh[kk][c4] = *(const float4*)&W[(kb + kk) * 64 + c4];
        }
        for (int i = tid; i < 1024; i += 128) {
            int k4 = (i & 15) << 2, r = i >> 4;
            int row = row0 + r;
            float4 v = (row < n) ? *(const float4*)&X[row * K + kb + k4]
                                 : make_float4(0.f, 0.f, 0.f, 0.f);
            Xsh[r][k4 + 0] = v.x; Xsh[r][k4 + 1] = v.y;
            Xsh[r][k4 + 2] = v.z; Xsh[r][k4 + 3] = v.w;
        }
        __syncthreads();
#pragma unroll 8
        for (int k = 0; k < 64; k++) {
            float4 wv = *(const float4*)&Wsh[k][tx << 2];
            float wc[4] = {wv.x, wv.y, wv.z, wv.w};
            float xr[8];
#pragma unroll
            for (int r = 0; r < 8; r++) xr[r] = Xsh[(ty << 3) + r][k];
#pragma unroll
            for (int r = 0; r < 8; r++)
#pragma unroll
                for (int c = 0; c < 4; c++) acc[r][c] = fmaf(xr[r], wc[c], acc[r][c]);
        }
        __syncthreads();
    }
    // attention vector slice for this thread's 4 columns
    float as[4], ad[4];
#pragma unroll
    for (int c = 0; c < 4; c++) {
        as[c] = __ldg(a_src + (tx << 2) + c);
        ad[c] = __ldg(a_dst + (tx << 2) + c);
    }
    int head = tx >> 3;  // 0 or 1
#pragma unroll
    for (int r = 0; r < 8; r++) {
        int row = row0 + (ty << 3) + r;
        if (row < n) {
            // fp16 gather table: 2 half2 per thread (8B store)
            __half2 p0 = __floats2half2_rn(acc[r][0], acc[r][1]);
            __half2 p1 = __floats2half2_rn(acc[r][2], acc[r][3]);
            *(__half2*)&g_hh[row * 32 + (tx << 1)] = p0;
            *(__half2*)&g_hh[row * 32 + (tx << 1) + 1] = p1;
        }
        float ps = 0.f, pd = 0.f;
#pragma unroll
        for (int c = 0; c < 4; c++) {
            ps = fmaf(acc[r][c], as[c], ps);
            pd = fmaf(acc[r][c], ad[c], pd);
        }
        // reduce across the 8-lane head group (tx bits 0..2 live in lane bits 0..2)
#pragma unroll
        for (int o = 4; o; o >>= 1) {
            ps += __shfl_xor_sync(FULLMASK, ps, o);
            pd += __shfl_xor_sync(FULLMASK, pd, o);
        }
        if (row < n && (tx & 7) == 0) {
            ((float*)g_asrc)[row * 2 + head] = ps;
            ((float*)g_adst)[row * 2 + head] = pd;
        }
    }
}

// ---------------- fused edge kernel: softmax + weighted gather (fp16 h) ----------------
// One warp per dst node, chunks of 32 edges (avg degree ~17 -> usually 1 chunk).
// Per chunk: lane-parallel logits -> warp max -> online rescale -> (src,p) packed
// per-head into smem uint2 -> broadcast gather-FMA loop (LDS.64 + LDG.32, MLP=4).
// lane owns channels {2*lane, 2*lane+1}; lanes 0-15 head0, 16-31 head1.
template <bool FIRST>
__global__ void edge_fused(const float* __restrict__ bias, int n) {
    __shared__ uint2 se[8][2][32];  // [warp][head][slot] = (src, p_bits)
    int w = (blockIdx.x * blockDim.x + threadIdx.x) >> 5;
    int lane = threadIdx.x & 31;
    int wl = (threadIdx.x >> 5) & 7;
    if (w >= n) return;
    int beg = g_rowptr[w], end = g_rowptr[w + 1];
    float2 ad = g_adst[w];
    bool head0 = lane < 16;
    const __half2* H = (const __half2*)g_hh;
    const uint2* q = &se[wl][head0 ? 0 : 1][0];

    float m0 = -1e30f, m1 = -1e30f;
    float s0 = 0.f, s1 = 0.f;
    float ax = 0.f, ay = 0.f;

    for (int base = beg; base < end; base += 32) {
        int cnt = min(32, end - base);
        int j = base + lane;
        bool act = j < end;
        // phase 1: lane-parallel logits
        int src = 0;
        float e0 = -1e30f, e1 = -1e30f;
        if (act) {
            src = g_colsrc[j];
            float2 asv = g_asrc[src];
            e0 = asv.x + ad.x; e0 = e0 >= 0.f ? e0 : 0.2f * e0;
            e1 = asv.y + ad.y; e1 = e1 >= 0.f ? e1 : 0.2f * e1;
        }
        float cm0 = e0, cm1 = e1;
#pragma unroll
        for (int o = 16; o; o >>= 1) {
            cm0 = fmaxf(cm0, __shfl_xor_sync(FULLMASK, cm0, o));
            cm1 = fmaxf(cm1, __shfl_xor_sync(FULLMASK, cm1, o));
        }
        float nm0 = fmaxf(m0, cm0), nm1 = fmaxf(m1, cm1);
        float sc0 = __expf(m0 - nm0), sc1 = __expf(m1 - nm1);  // 0 on first chunk
        s0 *= sc0; s1 *= sc1;
        float mysc = head0 ? sc0 : sc1;
        ax *= mysc; ay *= mysc;
        m0 = nm0; m1 = nm1;
        // phase 2: exp, partial sums, packed (src,p) per head
        if (act) {
            float p0 = __expf(e0 - m0);
            float p1 = __expf(e1 - m1);
            s0 += p0; s1 += p1;
            se[wl][0][lane] = make_uint2((unsigned)src, __float_as_uint(p0));
            se[wl][1][lane] = make_uint2((unsigned)src, __float_as_uint(p1));
        }
        __syncwarp();
        // phase 3: broadcast gather-FMA, unrolled x4 for MLP
        int t = 0;
        for (; t + 4 <= cnt; t += 4) {
            uint2 v0 = q[t], v1 = q[t + 1], v2 = q[t + 2], v3 = q[t + 3];
            __half2 h0 = __ldg(&H[v0.x * 32 + lane]);
            __half2 h1 = __ldg(&H[v1.x * 32 + lane]);
            __half2 h2 = __ldg(&H[v2.x * 32 + lane]);
            __half2 h3 = __ldg(&H[v3.x * 32 + lane]);
            float2 f0 = __half22float2(h0), f1 = __half22float2(h1);
            float2 f2 = __half22float2(h2), f3 = __half22float2(h3);
            float p0 = __uint_as_float(v0.y), p1 = __uint_as_float(v1.y);
            float p2 = __uint_as_float(v2.y), p3 = __uint_as_float(v3.y);
            ax = fmaf(p0, f0.x, ax); ay = fmaf(p0, f0.y, ay);
            ax = fmaf(p1, f1.x, ax); ay = fmaf(p1, f1.y, ay);
            ax = fmaf(p2, f2.x, ax); ay = fmaf(p2, f2.y, ay);
            ax = fmaf(p3, f3.x, ax); ay = fmaf(p3, f3.y, ay);
        }
        for (; t < cnt; t++) {
            uint2 v0 = q[t];
            float2 f = __half22float2(__ldg(&H[v0.x * 32 + lane]));
            float p0 = __uint_as_float(v0.y);
            ax = fmaf(p0, f.x, ax); ay = fmaf(p0, f.y, ay);
        }
        __syncwarp();
    }
    // final sum reduction (each lane holds a partial of its own edges, uniformly rescaled)
#pragma unroll
    for (int o = 16; o; o >>= 1) {
        s0 += __shfl_xor_sync(FULLMASK, s0, o);
        s1 += __shfl_xor_sync(FULLMASK, s1, o);
    }
    float iv = 1.0f / (head0 ? s0 : s1);
    float2 b = __ldg(&((const float2*)bias)[lane]);
    float ox = ax * iv + b.x;
    float oy = ay * iv + b.y;
    if (FIRST) {
        ((float2*)g_init)[w * 32 + lane] = make_float2(ox, oy);  // initial_x (pre-elu)
    } else {
        float2 rv = ((const float2*)g_init)[w * 32 + lane];
        ox += rv.x; oy += rv.y;
    }
    ox = ox > 0.f ? ox : __expf(ox) - 1.f;
    oy = oy > 0.f ? oy : __expf(oy) - 1.f;
    ((float2*)g_x)[w * 32 + lane] = make_float2(ox, oy);
}

// ---------------- output layer: hout = x @ W_out (64 -> 1), warp per node ----------------
__global__ void gemm_out(const float* __restrict__ Wout, int n) {
    int w = (blockIdx.x * blockDim.x + threadIdx.x) >> 5;
    int lane = threadIdx.x & 31;
    if (w >= n) return;
    float v = g_x[w * 64 + lane] * __ldg(Wout + lane) +
              g_x[w * 64 + 32 + lane] * __ldg(Wout + 32 + lane);
#pragma unroll
    for (int o = 16; o; o >>= 1) v += __shfl_xor_sync(FULLMASK, v, o);
    if (lane == 0) g_hout[w] = v;
}

__global__ void edge_out(const float* __restrict__ a_s, const float* __restrict__ a_d,
                         const float* __restrict__ b, float* __restrict__ out, int n) {
    int w = (blockIdx.x * blockDim.x + threadIdx.x) >> 5;
    int lane = threadIdx.x & 31;
    if (w >= n) return;
    int beg = g_rowptr[w], end = g_rowptr[w + 1];
    float asv = __ldg(a_s), adv = __ldg(a_d);
    float adT = g_hout[w] * adv;
    float m = -1e30f;
    for (int j = beg + lane; j < end; j += 32) {
        float hs = g_hout[g_colsrc[j]];
        float e = fmaf(hs, asv, adT);
        e = e >= 0.f ? e : 0.2f * e;
        m = fmaxf(m, e);
    }
#pragma unroll
    for (int o = 16; o; o >>= 1) m = fmaxf(m, __shfl_xor_sync(FULLMASK, m, o));
    float s = 0.f, accv = 0.f;
    for (int j = beg + lane; j < end; j += 32) {
        float hs = g_hout[g_colsrc[j]];
        float e = fmaf(hs, asv, adT);
        e = e >= 0.f ? e : 0.2f * e;
        float p = __expf(e - m);
        s += p;
        accv = fmaf(p, hs, accv);
    }
#pragma unroll
    for (int o = 16; o; o >>= 1) {
        s += __shfl_xor_sync(FULLMASK, s, o);
        accv += __shfl_xor_sync(FULLMASK, accv, o);
    }
    if (lane == 0) {
        float v = accv / s + __ldg(b);
        out[w] = 1.f / (1.f + __expf(-v));
    }
}

// ---------------- launcher ----------------
extern "C" void kernel_launch(void* const* d_in, const int* in_sizes, int n_in,
                              void* d_out, int out_size) {
    const float* node_attrs = (const float*)d_in[0];
    const int*   edge_index = (const int*)d_in[1];
    const float* W_in      = (const float*)d_in[2];
    const float* a_src_in  = (const float*)d_in[3];
    const float* a_dst_in  = (const float*)d_in[4];
    const float* b_in      = (const float*)d_in[5];
    const float* W_mid     = (const float*)d_in[6];
    const float* a_src_mid = (const float*)d_in[7];
    const float* a_dst_mid = (const float*)d_in[8];
    const float* b_mid     = (const float*)d_in[9];
    const float* W_out     = (const float*)d_in[10];
    const float* a_src_out = (const float*)d_in[11];
    const float* a_dst_out = (const float*)d_in[12];
    const float* b_out     = (const float*)d_in[13];
    float* out = (float*)d_out;

    int n = in_sizes[0] / 128;
    int e = in_sizes[1] / 2;

    const int tb = 256;
    // CSR build (graph identical for all layers)
    init_cnt<<<(n + tb - 1) / tb, tb>>>(n);
    hist<<<(e + tb - 1) / tb, tb>>>(edge_index, e);
    int nb = (n + SCAN_B - 1) / SCAN_B;
    scan1<<<nb, SCAN_B>>>(n);
    scan2<<<1, SCAN_B>>>(nb);
    scan3<<<nb, SCAN_B>>>(n, e + n);
    scatter<<<(e + n + tb - 1) / tb, tb>>>(edge_index, e, n);

    int gblocks = (n + 63) / 64;
    int wblocks = (n + 7) / 8;  // 8 warps per 256-thread block

    // input conv
    gemm_att<128><<<gblocks, 128>>>(node_attrs, W_in, a_src_in, a_dst_in, n);
    edge_fused<true><<<wblocks, 256>>>(b_in, n);

    // 6 mid convs (shared weights), residual from g_init
    for (int l = 0; l < 6; l++) {
        gemm_att<64><<<gblocks, 128>>>(nullptr, W_mid, a_src_mid, a_dst_mid, n);
        edge_fused<false><<<wblocks, 256>>>(b_mid, n);
    }

    // output conv + sigmoid
    gemm_out<<<wblocks, 256>>>(W_out, n);
    edge_out<<<wblocks, 256>>>(a_src_out, a_dst_out, b_out, out, n);
}